// round 10
// baseline (speedup 1.0000x reference)
#include <cuda_runtime.h>
#include <cuda_fp16.h>
#include <cstdint>

#define BATCH    8
#define GH       64
#define C0       64
#define NPTS     16384
#define NFREQ    10
#define HID      256
#define TILE_M   128
#define THREADS  256
#define HSH      272                 // halves per h row (word stride 136 == 8 mod 32)
#define CHUNKH   10752               // halves per 32-k weight chunk (incl pads)
#define SUPERH   (2 * CHUNKH)        // 64-k superchunk (43 KB)

// ---------------- device scratch (static, allocation-free) ----------------
__device__ float  g_gamma[BATCH * HID];
__device__ float  g_beta [BATCH * HID];
__device__ __half g_WT   [4 * 8 * CHUNKH];   // fragment-packed fp16 weights
__device__ float  g_lvl1 [BATCH * 32 * 32 * C0];
__device__ float  g_lvl2 [BATCH * 16 * 16 * C0];

// ---------------- helpers ----------------
__device__ __forceinline__ uint32_t smem_u32(const void* p) {
    uint32_t a;
    asm("{ .reg .u64 t; cvta.to.shared.u64 t, %1; cvt.u32.u64 %0, t; }" : "=r"(a) : "l"(p));
    return a;
}
__device__ __forceinline__ float tanh_fast(float y) {     // accurate (output stage)
    float e; asm("ex2.approx.f32 %0, %1;" : "=f"(e) : "f"(y * 2.8853900817779268f));
    float r; asm("rcp.approx.f32 %0, %1;" : "=f"(r) : "f"(e + 1.0f));
    return 1.0f - 2.0f * r;
}
__device__ __forceinline__ float tanh_hw(float x) {       // 1-MUFU approx (hidden layers)
    float r; asm("tanh.approx.f32 %0, %1;" : "=f"(r) : "f"(x)); return r;
}
__device__ __forceinline__ float gelu_f(float x) {
    float u = 0.7978845608028654f * fmaf(0.044715f * x, x * x, x);
    return 0.5f * x * (1.0f + tanh_hw(u));
}
__device__ __forceinline__ void cp16(uint32_t saddr, const void* g) {
    asm volatile("cp.async.cg.shared.global [%0], [%1], 16;" :: "r"(saddr), "l"(g));
}
__device__ __forceinline__ void mma_f16(float* d, const uint32_t* a,
                                        uint32_t b0, uint32_t b1) {
    asm volatile(
        "mma.sync.aligned.m16n8k16.row.col.f32.f16.f16.f32 "
        "{%0,%1,%2,%3}, {%4,%5,%6,%7}, {%8,%9}, {%0,%1,%2,%3};"
        : "+f"(d[0]), "+f"(d[1]), "+f"(d[2]), "+f"(d[3])
        : "r"(a[0]), "r"(a[1]), "r"(a[2]), "r"(a[3]), "r"(b0), "r"(b1));
}
// full-k permutation: within each 16-block, place k at ((k>>1)&3)*4 + ((k>>3)&1)*2 + (k&1)
__device__ __host__ __forceinline__ int permfull(int k) {
    return (k & ~15) | ((((k >> 1) & 3) << 2) | (((k >> 3) & 1) << 1) | (k & 1));
}

// ---------------- prep: FiLM params ----------------
__global__ void prep_ctx_kernel(const float* __restrict__ cv,
                                const float* __restrict__ Wc,
                                const float* __restrict__ bc) {
    int b = blockIdx.x, c = threadIdx.x;
    float g  = bc[c];
    float bt = bc[HID + c];
#pragma unroll 8
    for (int k = 0; k < C0; k++) {
        float v = cv[b * C0 + k];
        g  += v * Wc[k * 2 * HID + c];
        bt += v * Wc[k * 2 * HID + HID + c];
    }
    g_gamma[b * HID + c] = g + 1.0f;
    g_beta [b * HID + c] = bt;
}

// ---------------- prep: pack weights (fp16, per-thread fragment order) -----
// chunk layout (halves): [nw:4][s:2][cq:4][r:8][nt:8 x 4 halves][pad 8]
//   r-row stride 40, (s,cq) block 336, s block 1344, nw block 2688.
// halves per nt: k = 2cq, 2cq+1, 2cq+8, 2cq+9 (within the 16-k step).
// layer-0 K remap: [0..41]->rows 0..41, [42..43] zero, [44..235]->rows 42..233,
// [236..255] zero (matches the h-tile layout).
__global__ void prep_wt_kernel(const float* __restrict__ W0,
                               const float* __restrict__ W1,
                               const float* __restrict__ W2,
                               const float* __restrict__ W3) {
    int idx = blockIdx.x * blockDim.x + threadIdx.x;   // 4 * 8 * CHUNKH
    int l   = idx / (8 * CHUNKH);
    int rem = idx % (8 * CHUNKH);
    int c   = rem / CHUNKH;  rem %= CHUNKH;
    int nw  = rem / 2688;    rem %= 2688;
    int s   = rem / 1344;    rem %= 1344;
    int cq  = rem / 336;     rem %= 336;
    float v = 0.0f;
    if (rem < 320) {
        int r   = rem / 40;
        int pos = rem % 40;
        if (pos < 32) {
            int nt = pos >> 2, q = pos & 3;
            int k  = c * 32 + s * 16 + 2 * cq + (q & 1) + ((q >> 1) << 3);
            int n  = nw * 64 + nt * 8 + r;
            if (l == 0) {
                if (k < 42)                  v = W0[k * HID + n];
                else if (k >= 44 && k < 236) v = W0[(k - 2) * HID + n];
            } else if (l == 1) v = W1[k * HID + n];
            else if (l == 2)   v = W2[k * HID + n];
            else               v = W3[k * HID + n];
        }
    }
    g_WT[idx] = __float2half_rn(v);
}

// ---------------- prep: antialiased bilinear pyramid (jax.image.resize) ----
template <int HL>
__global__ void resize_kernel(const float* __restrict__ src) {
    int idx = blockIdx.x * blockDim.x + threadIdx.x;
    int c = idx & (C0 - 1);
    int v = idx >> 6;
    int x = v % HL;
    int y = (v / HL) % HL;
    int b = v / (HL * HL);

    const float scale = (float)(GH / HL);
    const int   T     = 2 * (GH / HL);

    float sy = (y + 0.5f) * scale - 0.5f;
    float sx = (x + 0.5f) * scale - 0.5f;
    int s0y = (int)floorf(sy - scale) + 1;
    int s0x = (int)floorf(sx - scale) + 1;

    float wy[8], wx[8];
    float sumy = 0.f, sumx = 0.f;
#pragma unroll
    for (int t = 0; t < T; t++) {
        int s = s0y + t;
        float w = 1.0f - fabsf((float)s - sy) / scale;
        w = (s >= 0 && s < GH && w > 0.f) ? w : 0.f;
        wy[t] = w; sumy += w;
        s = s0x + t;
        w = 1.0f - fabsf((float)s - sx) / scale;
        w = (s >= 0 && s < GH && w > 0.f) ? w : 0.f;
        wx[t] = w; sumx += w;
    }
    float inv = 1.0f / (sumy * sumx);

    float acc = 0.f;
#pragma unroll
    for (int a = 0; a < T; a++) {
        if (wy[a] == 0.f) continue;
        const float* row = src + ((((b * GH) + (s0y + a)) * GH) << 6) + c;
        float pacc = 0.f;
#pragma unroll
        for (int t = 0; t < T; t++) {
            if (wx[t] == 0.f) continue;
            pacc += wx[t] * row[(s0x + t) << 6];
        }
        acc += wy[a] * pacc;
    }
    float* dst = (HL == 32) ? g_lvl1 : g_lvl2;
    dst[idx] = acc * inv;
}

// ---------------- superchunk fill: linear 43 KB copy (256 threads) ---------
__device__ __forceinline__ void fill_super(__half* wsm, const __half* wt_l,
                                           int sc, int tid) {
    uint32_t sb = smem_u32(wsm);
    const char* src = (const char*)(wt_l + sc * SUPERH);
#pragma unroll
    for (int s = 0; s < 10; s++) {
        int u = tid + s * THREADS;          // 16B units, 2688 total
        cp16(sb + u * 16, src + (size_t)u * 16);
    }
    if (tid < 128) { int u = 2560 + tid; cp16(sb + u * 16, src + (size_t)u * 16); }
    asm volatile("cp.async.commit_group;" ::: "memory");
}

// ---------------- main fused decoder (fp16 HMMA, 64x64 warp tiles) ---------
__global__ __launch_bounds__(THREADS, 1)
void decoder_kernel(const float* __restrict__ fg,
                    const float* __restrict__ coords,
                    const float* __restrict__ b0, const float* __restrict__ b1,
                    const float* __restrict__ b2, const float* __restrict__ b3,
                    const float* __restrict__ Wout, const float* __restrict__ bout,
                    float* __restrict__ out) {
    extern __shared__ char smem_raw[];
    __half* wbuf   = (__half*)smem_raw;                       // 2 * SUPERH
    __half* h_s    = wbuf + 2 * SUPERH;                       // 128 * 272
    float*  bias_s = (float*)(h_s + TILE_M * HSH);            // 4*256
    float*  gam_s  = bias_s + 4 * HID;
    float*  bet_s  = gam_s + HID;
    float*  wo_s   = bet_s + HID;                             // 3*256 permuted
    float*  bo_s   = wo_s + 3 * HID;                          // 4

    const int tid  = threadIdx.x;
    const int lane = tid & 31;
    const int wid  = tid >> 5;
    const int mw   = wid & 1,  nw = wid >> 1;   // 2 x 4 warp grid
    const int m0   = mw * 64,  n0 = nw * 64;
    const int r    = lane >> 2, cq = lane & 3;
    const int b    = blockIdx.x >> 7;
    const int n0p  = (blockIdx.x & 127) * TILE_M;

    // prefill layer-0 superchunk 0 (overlaps feature build)
    fill_super(wbuf, g_WT, 0, tid);

    // stage per-CTA params
    gam_s[tid]  = g_gamma[b * HID + tid];
    bet_s[tid]  = g_beta [b * HID + tid];
    bias_s[tid]           = b0[tid];
    bias_s[HID + tid]     = b1[tid];
    bias_s[2 * HID + tid] = b2[tid];
    bias_s[3 * HID + tid] = b3[tid];
    // Wout staged permuted: wo_s[o*256 + kp] = Wout[invperm(kp)*3 + o]
    for (int j = tid; j < 3 * HID; j += THREADS) {
        int o = j >> 8, kp = j & 255;
        int pos = kp & 15;
        int k = (kp & ~15) | (((pos >> 1) & 1) << 3) | (((pos >> 2) & 3) << 1) | (pos & 1);
        wo_s[j] = Wout[k * 3 + o];
    }
    if (tid < 3) bo_s[tid] = bout[tid];

    // ---- build features (fp16, permuted k): 2 threads per point ----
    {
        int p = tid >> 1, q = tid & 1;
        float cy = coords[(n0p + p) * 2 + 0];
        float cx = coords[(n0p + p) * 2 + 1];
        __half* hp = h_s + p * HSH;

        // each thread handles 5 posenc freqs (q*5 .. q*5+4)
        {
            float fr = 3.14159265358979323846f * (float)(1 << (5 * q));
#pragma unroll
            for (int f5 = 0; f5 < 5; f5++) {
                int f = q * 5 + f5;
                float sv, cvv;
                sincosf(cy * fr, &sv, &cvv);
                hp[permfull(2 + 4 * f + 0)] = __float2half_rn(sv);
                hp[permfull(2 + 4 * f + 2)] = __float2half_rn(cvv);
                sincosf(cx * fr, &sv, &cvv);
                hp[permfull(2 + 4 * f + 1)] = __float2half_rn(sv);
                hp[permfull(2 + 4 * f + 3)] = __float2half_rn(cvv);
                fr *= 2.0f;
            }
        }
        if (q == 0) {
            hp[permfull(0)] = __float2half_rn(cy);
            hp[permfull(1)] = __float2half_rn(cx);
            hp[permfull(42)] = __float2half_rn(0.f);
            hp[permfull(43)] = __float2half_rn(0.f);
#pragma unroll
            for (int k = 236; k < 256; k++) hp[permfull(k)] = __float2half_rn(0.f);
        }

#pragma unroll
        for (int lvl = 0; lvl < 3; lvl++) {
            int Hl = GH >> lvl;
            const float* G = (lvl == 0) ? fg : ((lvl == 1) ? g_lvl1 : g_lvl2);
            float yf = (cy + 1.0f) * 0.5f * (float)(Hl - 1);
            float xf = (cx + 1.0f) * 0.5f * (float)(Hl - 1);
            float y0f = floorf(yf), x0f = floorf(xf);
            float wy = yf - y0f, wx = xf - x0f;
            int y0 = min(max((int)y0f, 0), Hl - 1);
            int x0 = min(max((int)x0f, 0), Hl - 1);
            int y1 = min(y0 + 1, Hl - 1);
            int x1 = min(x0 + 1, Hl - 1);
            const float* p00 = G + ((((b * Hl) + y0) * Hl + x0) << 6);
            const float* p01 = G + ((((b * Hl) + y0) * Hl + x1) << 6);
            const float* p10 = G + ((((b * Hl) + y1) * Hl + x0) << 6);
            const float* p11 = G + ((((b * Hl) + y1) * Hl + x1) << 6);
            float omx = 1.0f - wx, omy = 1.0f - wy;
            int base = 44 + lvl * 64 + q * 32;
#pragma unroll
            for (int cc = 0; cc < 8; cc++) {
                int c = q * 32 + cc * 4;
                float4 v00 = *(const float4*)(p00 + c);
                float4 v01 = *(const float4*)(p01 + c);
                float4 v10 = *(const float4*)(p10 + c);
                float4 v11 = *(const float4*)(p11 + c);
                hp[permfull(base + cc * 4 + 0)] = __float2half_rn(
                    (v00.x * omx + v01.x * wx) * omy + (v10.x * omx + v11.x * wx) * wy);
                hp[permfull(base + cc * 4 + 1)] = __float2half_rn(
                    (v00.y * omx + v01.y * wx) * omy + (v10.y * omx + v11.y * wx) * wy);
                hp[permfull(base + cc * 4 + 2)] = __float2half_rn(
                    (v00.z * omx + v01.z * wx) * omy + (v10.z * omx + v11.z * wx) * wy);
                hp[permfull(base + cc * 4 + 3)] = __float2half_rn(
                    (v00.w * omx + v01.w * wx) * omy + (v10.w * omx + v11.w * wx) * wy);
            }
        }
    }

    // ---- 4 FiLM'd MLP layers on tensor cores (fp16 m16n8k16) ----
    for (int l = 0; l < 4; l++) {
        float acc[4][8][4];
#pragma unroll
        for (int i = 0; i < 4; i++)
#pragma unroll
            for (int j = 0; j < 8; j++)
#pragma unroll
                for (int v = 0; v < 4; v++) acc[i][j][v] = 0.f;

        for (int sc = 0; sc < 4; sc++) {
            asm volatile("cp.async.wait_group 0;" ::: "memory");
            __syncthreads();
            if (!(l == 3 && sc == 3)) {
                int nl = l, nsc = sc + 1;
                if (nsc == 4) { nsc = 0; nl = l + 1; }
                fill_super(wbuf + ((sc + 1) & 1) * SUPERH,
                           g_WT + nl * (8 * CHUNKH), nsc, tid);
            }

            const __half* sbuf = wbuf + (sc & 1) * SUPERH;
#pragma unroll
            for (int cc = 0; cc < 2; cc++) {
                const __half* wb = sbuf + cc * CHUNKH + nw * 2688;
#pragma unroll
                for (int s = 0; s < 2; s++) {
                    const int kpos = sc * 64 + cc * 32 + s * 16 + cq * 4;
                    uint32_t a[4][4];
#pragma unroll
                    for (int mt = 0; mt < 4; mt++) {
                        int row = m0 + mt * 16 + r;
                        uint2 L0 = *(const uint2*)(h_s + row * HSH + kpos);
                        uint2 L1 = *(const uint2*)(h_s + (row + 8) * HSH + kpos);
                        a[mt][0] = L0.x; a[mt][1] = L1.x;
                        a[mt][2] = L0.y; a[mt][3] = L1.y;
                    }
                    const __half* bp = wb + s * 1344 + cq * 336 + r * 40;
#pragma unroll
                    for (int j = 0; j < 4; j++) {
                        uint4 B = *(const uint4*)(bp + j * 8);
#pragma unroll
                        for (int mt = 0; mt < 4; mt++) {
                            mma_f16(acc[mt][2 * j],     a[mt], B.x, B.y);
                            mma_f16(acc[mt][2 * j + 1], a[mt], B.z, B.w);
                        }
                    }
                }
            }
        }
        __syncthreads();   // all A-reads of h done before epilogue writes

        // ---- epilogue: bias + FiLM + gelu -> fp16, write back permuted ----
#pragma unroll
        for (int nt = 0; nt < 8; nt++) {
            int n  = n0 + nt * 8 + 2 * cq;
            int pp = (n >> 4) * 16 + cq * 4 + 2 * (nt & 1);   // permuted position
            float g0 = gam_s[n],  g1 = gam_s[n + 1];
            float e0 = bet_s[n],  e1 = bet_s[n + 1];
            float i0 = bias_s[l * HID + n], i1 = bias_s[l * HID + n + 1];
#pragma unroll
            for (int mt = 0; mt < 4; mt++) {
                int p0 = m0 + mt * 16 + r;
                *(__half2*)(h_s + p0 * HSH + pp) = __floats2half2_rn(
                    gelu_f((acc[mt][nt][0] + i0) * g0 + e0),
                    gelu_f((acc[mt][nt][1] + i1) * g1 + e1));
                *(__half2*)(h_s + (p0 + 8) * HSH + pp) = __floats2half2_rn(
                    gelu_f((acc[mt][nt][2] + i0) * g0 + e0),
                    gelu_f((acc[mt][nt][3] + i1) * g1 + e1));
            }
        }
        __syncthreads();
    }

    // ---- output head: tanh(h @ Wout + bout), permuted-k dot products ----
    {
        int p = tid & 127, pr = tid >> 7;     // pr=0 -> o 0,1 ; pr=1 -> o 2
        const __half2* hp = (const __half2*)(h_s + p * HSH);
        int olo = pr * 2, ohi = (pr == 0) ? 2 : 3;
        for (int o = olo; o < ohi; o++) {
            const float* wp = wo_s + o * HID;
            float a0 = 0.f, a1 = 0.f;
#pragma unroll 16
            for (int k2 = 0; k2 < HID / 2; k2 += 2) {
                float2 h0 = __half22float2(hp[k2]);
                float2 h1 = __half22float2(hp[k2 + 1]);
                a0 += h0.x * wp[2 * k2]     + h0.y * wp[2 * k2 + 1];
                a1 += h1.x * wp[2 * k2 + 2] + h1.y * wp[2 * k2 + 3];
            }
            float acc = bo_s[o] + a0 + a1;
            out[((size_t)b * NPTS + n0p + p) * 3 + o] = tanh_fast(acc);
        }
    }
}

// ---------------- launch ----------------
extern "C" void kernel_launch(void* const* d_in, const int* in_sizes, int n_in,
                              void* d_out, int out_size) {
    const float* fg = (const float*)d_in[0];
    const float* cv = (const float*)d_in[1];
    const float* co = (const float*)d_in[2];
    const float* Wc = (const float*)d_in[3];
    const float* bc = (const float*)d_in[4];
    const float* W0 = (const float*)d_in[5];
    const float* b0 = (const float*)d_in[6];
    const float* W1 = (const float*)d_in[7];
    const float* b1 = (const float*)d_in[8];
    const float* W2 = (const float*)d_in[9];
    const float* b2 = (const float*)d_in[10];
    const float* W3 = (const float*)d_in[11];
    const float* b3 = (const float*)d_in[12];
    const float* Wo = (const float*)d_in[13];
    const float* bo = (const float*)d_in[14];
    float* out = (float*)d_out;

    const int smemB = (2 * SUPERH + TILE_M * HSH) * 2 +
                      (4 * HID + HID + HID + 3 * HID + 4) * 4;
    cudaFuncSetAttribute(decoder_kernel,
                         cudaFuncAttributeMaxDynamicSharedMemorySize, smemB);

    prep_ctx_kernel<<<BATCH, HID>>>(cv, Wc, bc);
    prep_wt_kernel<<<(4 * 8 * CHUNKH) / 256, 256>>>(W0, W1, W2, W3);
    resize_kernel<32><<<(BATCH * 32 * 32 * C0) / 256, 256>>>(fg);
    resize_kernel<16><<<(BATCH * 16 * 16 * C0) / 256, 256>>>(fg);
    decoder_kernel<<<BATCH * (NPTS / TILE_M), THREADS, smemB>>>(
        fg, co, b0, b1, b2, b3, Wo, bo, out);
}

// round 11
// speedup vs baseline: 1.1102x; 1.1102x over previous
#include <cuda_runtime.h>
#include <cuda_fp16.h>
#include <cstdint>

#define BATCH    8
#define GH       64
#define C0       64
#define NPTS     16384
#define NFREQ    10
#define HID      256
#define TILE_M   64
#define THREADS  256
#define HSH      272                 // halves per h row (word stride 136 == 8 mod 32)
#define CHUNKH   10752               // halves per 32-k weight chunk (incl pads)

// ---------------- device scratch (static, allocation-free) ----------------
__device__ float  g_gamma[BATCH * HID];
__device__ float  g_beta [BATCH * HID];
__device__ __half g_WT   [4 * 8 * CHUNKH];   // fragment-packed fp16 weights
__device__ float  g_lvl1 [BATCH * 32 * 32 * C0];
__device__ float  g_lvl2 [BATCH * 16 * 16 * C0];

// ---------------- helpers ----------------
__device__ __forceinline__ uint32_t smem_u32(const void* p) {
    uint32_t a;
    asm("{ .reg .u64 t; cvta.to.shared.u64 t, %1; cvt.u32.u64 %0, t; }" : "=r"(a) : "l"(p));
    return a;
}
__device__ __forceinline__ float tanh_fast(float y) {     // accurate (output stage)
    float e; asm("ex2.approx.f32 %0, %1;" : "=f"(e) : "f"(y * 2.8853900817779268f));
    float r; asm("rcp.approx.f32 %0, %1;" : "=f"(r) : "f"(e + 1.0f));
    return 1.0f - 2.0f * r;
}
__device__ __forceinline__ float tanh_hw(float x) {       // 1-MUFU approx (hidden layers)
    float r; asm("tanh.approx.f32 %0, %1;" : "=f"(r) : "f"(x)); return r;
}
__device__ __forceinline__ float gelu_f(float x) {
    float u = 0.7978845608028654f * fmaf(0.044715f * x, x * x, x);
    return 0.5f * x * (1.0f + tanh_hw(u));
}
__device__ __forceinline__ void cp16(uint32_t saddr, const void* g) {
    asm volatile("cp.async.cg.shared.global [%0], [%1], 16;" :: "r"(saddr), "l"(g));
}
__device__ __forceinline__ void mma_f16(float* d, const uint32_t* a,
                                        uint32_t b0, uint32_t b1) {
    asm volatile(
        "mma.sync.aligned.m16n8k16.row.col.f32.f16.f16.f32 "
        "{%0,%1,%2,%3}, {%4,%5,%6,%7}, {%8,%9}, {%0,%1,%2,%3};"
        : "+f"(d[0]), "+f"(d[1]), "+f"(d[2]), "+f"(d[3])
        : "r"(a[0]), "r"(a[1]), "r"(a[2]), "r"(a[3]), "r"(b0), "r"(b1));
}
// full-k permutation: within each 16-block, place k at ((k>>1)&3)*4 + ((k>>3)&1)*2 + (k&1)
__device__ __host__ __forceinline__ int permfull(int k) {
    return (k & ~15) | ((((k >> 1) & 3) << 2) | (((k >> 3) & 1) << 1) | (k & 1));
}

// ================== merged prep (one launch) ==================
// blocks [0,2048): resize lvl1 (HL=32); [2048,2560): resize lvl2 (HL=16);
// [2560,3904): weight pack; [3904,3912): FiLM ctx.

template <int HL>
__device__ void resize_body(int bid, int tid, const float* __restrict__ src) {
    int idx = bid * 256 + tid;
    int c = idx & (C0 - 1);
    int v = idx >> 6;
    int x = v % HL;
    int y = (v / HL) % HL;
    int b = v / (HL * HL);

    const float scale = (float)(GH / HL);
    const int   T     = 2 * (GH / HL);

    float sy = (y + 0.5f) * scale - 0.5f;
    float sx = (x + 0.5f) * scale - 0.5f;
    int s0y = (int)floorf(sy - scale) + 1;
    int s0x = (int)floorf(sx - scale) + 1;

    float wy[8], wx[8];
    float sumy = 0.f, sumx = 0.f;
#pragma unroll
    for (int t = 0; t < T; t++) {
        int s = s0y + t;
        float w = 1.0f - fabsf((float)s - sy) / scale;
        w = (s >= 0 && s < GH && w > 0.f) ? w : 0.f;
        wy[t] = w; sumy += w;
        s = s0x + t;
        w = 1.0f - fabsf((float)s - sx) / scale;
        w = (s >= 0 && s < GH && w > 0.f) ? w : 0.f;
        wx[t] = w; sumx += w;
    }
    float inv = 1.0f / (sumy * sumx);

    float acc = 0.f;
#pragma unroll
    for (int a = 0; a < T; a++) {
        if (wy[a] == 0.f) continue;
        const float* row = src + ((((b * GH) + (s0y + a)) * GH) << 6) + c;
        float pacc = 0.f;
#pragma unroll
        for (int t = 0; t < T; t++) {
            if (wx[t] == 0.f) continue;
            pacc += wx[t] * row[(s0x + t) << 6];
        }
        acc += wy[a] * pacc;
    }
    float* dst = (HL == 32) ? g_lvl1 : g_lvl2;
    dst[idx] = acc * inv;
}

__device__ void prep_wt_body(int bid, int tid,
                             const float* __restrict__ W0,
                             const float* __restrict__ W1,
                             const float* __restrict__ W2,
                             const float* __restrict__ W3) {
    int idx = bid * 256 + tid;                 // 4 * 8 * CHUNKH
    int l   = idx / (8 * CHUNKH);
    int rem = idx % (8 * CHUNKH);
    int c   = rem / CHUNKH;  rem %= CHUNKH;
    int nw  = rem / 2688;    rem %= 2688;
    int s   = rem / 1344;    rem %= 1344;
    int cq  = rem / 336;     rem %= 336;
    float v = 0.0f;
    if (rem < 320) {
        int r   = rem / 40;
        int pos = rem % 40;
        if (pos < 32) {
            int nt = pos >> 2, q = pos & 3;
            int k  = c * 32 + s * 16 + 2 * cq + (q & 1) + ((q >> 1) << 3);
            int n  = nw * 64 + nt * 8 + r;
            if (l == 0) {
                if (k < 42)                  v = W0[k * HID + n];
                else if (k >= 44 && k < 236) v = W0[(k - 2) * HID + n];
            } else if (l == 1) v = W1[k * HID + n];
            else if (l == 2)   v = W2[k * HID + n];
            else               v = W3[k * HID + n];
        }
    }
    g_WT[idx] = __float2half_rn(v);
}

__device__ void prep_ctx_body(int b, int c,
                              const float* __restrict__ cv,
                              const float* __restrict__ Wc,
                              const float* __restrict__ bc) {
    float g  = bc[c];
    float bt = bc[HID + c];
#pragma unroll 8
    for (int k = 0; k < C0; k++) {
        float v = cv[b * C0 + k];
        g  += v * Wc[k * 2 * HID + c];
        bt += v * Wc[k * 2 * HID + HID + c];
    }
    g_gamma[b * HID + c] = g + 1.0f;
    g_beta [b * HID + c] = bt;
}

__global__ void prep_all_kernel(const float* __restrict__ fg,
                                const float* __restrict__ cv,
                                const float* __restrict__ Wc,
                                const float* __restrict__ bc,
                                const float* __restrict__ W0,
                                const float* __restrict__ W1,
                                const float* __restrict__ W2,
                                const float* __restrict__ W3) {
    int bid = blockIdx.x, tid = threadIdx.x;
    if (bid < 2048)       resize_body<32>(bid, tid, fg);
    else if (bid < 2560)  resize_body<16>(bid - 2048, tid, fg);
    else if (bid < 3904)  prep_wt_body(bid - 2560, tid, W0, W1, W2, W3);
    else                  prep_ctx_body(bid - 3904, tid, cv, Wc, bc);
}

// ---------------- weight chunk fill: linear 21 KB copy (256 threads) -------
__device__ __forceinline__ void fill_chunk(__half* wsm, const __half* wt_l,
                                           int c, int tid) {
    uint32_t sb = smem_u32(wsm);
    const char* src = (const char*)(wt_l + c * CHUNKH);
#pragma unroll
    for (int s = 0; s < 5; s++) {
        int u = tid + s * THREADS;          // 16B units, 1344 total
        cp16(sb + u * 16, src + (size_t)u * 16);
    }
    if (tid < 64) { int u = 1280 + tid; cp16(sb + u * 16, src + (size_t)u * 16); }
    asm volatile("cp.async.commit_group;" ::: "memory");
}

// ---------------- main fused decoder (mma.sync fp16, 2 CTAs/SM) ------------
__global__ __launch_bounds__(THREADS, 2)
void decoder_kernel(const float* __restrict__ fg,
                    const float* __restrict__ coords,
                    const float* __restrict__ b0, const float* __restrict__ b1,
                    const float* __restrict__ b2, const float* __restrict__ b3,
                    const float* __restrict__ Wout, const float* __restrict__ bout,
                    float* __restrict__ out) {
    extern __shared__ char smem_raw[];
    __half* wbuf   = (__half*)smem_raw;                       // 2 * CHUNKH
    __half* h_s    = wbuf + 2 * CHUNKH;                       // 64 * 272
    float*  bias_s = (float*)(h_s + TILE_M * HSH);            // 4*256
    float*  gam_s  = bias_s + 4 * HID;
    float*  bet_s  = gam_s + HID;
    float*  wo_s   = bet_s + HID;                             // 3*256, straight [n][o]
    float*  bo_s   = wo_s + 3 * HID;                          // 4
    float*  red_s  = bo_s + 4;                                // 64*4*3

    const int tid  = threadIdx.x;
    const int lane = tid & 31;
    const int wid  = tid >> 5;
    const int mw   = wid & 1,  nw = wid >> 1;
    const int m0   = mw * 32,  n0 = nw * 64;
    const int r    = lane >> 2, cq = lane & 3;
    const int b    = blockIdx.x >> 8;
    const int n0p  = (blockIdx.x & 255) * TILE_M;

    // prefill layer-0 chunk 0 (overlaps feature build)
    fill_chunk(wbuf, g_WT, 0, tid);

    // stage per-CTA params
    gam_s[tid]  = g_gamma[b * HID + tid];
    bet_s[tid]  = g_beta [b * HID + tid];
    bias_s[tid]           = b0[tid];
    bias_s[HID + tid]     = b1[tid];
    bias_s[2 * HID + tid] = b2[tid];
    bias_s[3 * HID + tid] = b3[tid];
    for (int j = tid; j < 3 * HID; j += THREADS) wo_s[j] = Wout[j];
    if (tid < 3) bo_s[tid] = bout[tid];

    // ---- build features (fp16, permuted k): 4 threads per point ----
    {
        int p = tid >> 2, q = tid & 3;
        float cy = coords[(n0p + p) * 2 + 0];
        float cx = coords[(n0p + p) * 2 + 1];
        __half* hp = h_s + p * HSH;

        if (q == 0) {
            hp[permfull(0)] = __float2half_rn(cy);
            hp[permfull(1)] = __float2half_rn(cx);
            float fr = 3.14159265358979323846f;
#pragma unroll
            for (int f = 0; f < NFREQ; f++) {
                float sv, cvv;
                sincosf(cy * fr, &sv, &cvv);
                hp[permfull(2 + 4 * f + 0)] = __float2half_rn(sv);
                hp[permfull(2 + 4 * f + 2)] = __float2half_rn(cvv);
                sincosf(cx * fr, &sv, &cvv);
                hp[permfull(2 + 4 * f + 1)] = __float2half_rn(sv);
                hp[permfull(2 + 4 * f + 3)] = __float2half_rn(cvv);
                fr *= 2.0f;
            }
            hp[permfull(42)] = __float2half_rn(0.f);
            hp[permfull(43)] = __float2half_rn(0.f);
#pragma unroll
            for (int k = 236; k < 256; k++) hp[permfull(k)] = __float2half_rn(0.f);
        }

#pragma unroll
        for (int lvl = 0; lvl < 3; lvl++) {
            int Hl = GH >> lvl;
            const float* G = (lvl == 0) ? fg : ((lvl == 1) ? g_lvl1 : g_lvl2);
            float yf = (cy + 1.0f) * 0.5f * (float)(Hl - 1);
            float xf = (cx + 1.0f) * 0.5f * (float)(Hl - 1);
            float y0f = floorf(yf), x0f = floorf(xf);
            float wy = yf - y0f, wx = xf - x0f;
            int y0 = min(max((int)y0f, 0), Hl - 1);
            int x0 = min(max((int)x0f, 0), Hl - 1);
            int y1 = min(y0 + 1, Hl - 1);
            int x1 = min(x0 + 1, Hl - 1);
            const float* p00 = G + ((((b * Hl) + y0) * Hl + x0) << 6);
            const float* p01 = G + ((((b * Hl) + y0) * Hl + x1) << 6);
            const float* p10 = G + ((((b * Hl) + y1) * Hl + x0) << 6);
            const float* p11 = G + ((((b * Hl) + y1) * Hl + x1) << 6);
            float omx = 1.0f - wx, omy = 1.0f - wy;
            int base = 44 + lvl * 64 + q * 16;
#pragma unroll
            for (int cc = 0; cc < 4; cc++) {
                int c = q * 16 + cc * 4;
                float4 v00 = *(const float4*)(p00 + c);
                float4 v01 = *(const float4*)(p01 + c);
                float4 v10 = *(const float4*)(p10 + c);
                float4 v11 = *(const float4*)(p11 + c);
                hp[permfull(base + cc * 4 + 0)] = __float2half_rn(
                    (v00.x * omx + v01.x * wx) * omy + (v10.x * omx + v11.x * wx) * wy);
                hp[permfull(base + cc * 4 + 1)] = __float2half_rn(
                    (v00.y * omx + v01.y * wx) * omy + (v10.y * omx + v11.y * wx) * wy);
                hp[permfull(base + cc * 4 + 2)] = __float2half_rn(
                    (v00.z * omx + v01.z * wx) * omy + (v10.z * omx + v11.z * wx) * wy);
                hp[permfull(base + cc * 4 + 3)] = __float2half_rn(
                    (v00.w * omx + v01.w * wx) * omy + (v10.w * omx + v11.w * wx) * wy);
            }
        }
    }

    // ---- 4 FiLM'd MLP layers on tensor cores (fp16 m16n8k16) ----
    for (int l = 0; l < 4; l++) {
        const __half* WTl = g_WT + l * (8 * CHUNKH);

        float acc[2][8][4];
#pragma unroll
        for (int i = 0; i < 2; i++)
#pragma unroll
            for (int j = 0; j < 8; j++)
#pragma unroll
                for (int v = 0; v < 4; v++) acc[i][j][v] = 0.f;

        for (int c = 0; c < 8; c++) {
            asm volatile("cp.async.wait_group 0;" ::: "memory");
            __syncthreads();
            if (c < 7)      fill_chunk(wbuf + ((c + 1) & 1) * CHUNKH, WTl, c + 1, tid);
            else if (l < 3) fill_chunk(wbuf + ((c + 1) & 1) * CHUNKH,
                                       g_WT + (l + 1) * (8 * CHUNKH), 0, tid);

            const __half* wb = wbuf + (c & 1) * CHUNKH + nw * 2688;
#pragma unroll
            for (int s = 0; s < 2; s++) {
                const int kpos = c * 32 + s * 16 + cq * 4;   // halves within row
                uint32_t a[2][4];
#pragma unroll
                for (int mt = 0; mt < 2; mt++) {
                    int row = m0 + mt * 16 + r;
                    uint2 L0 = *(const uint2*)(h_s + row * HSH + kpos);
                    uint2 L1 = *(const uint2*)(h_s + (row + 8) * HSH + kpos);
                    a[mt][0] = L0.x; a[mt][1] = L1.x;
                    a[mt][2] = L0.y; a[mt][3] = L1.y;
                }
                const __half* bp = wb + s * 1344 + cq * 336 + r * 40;
#pragma unroll
                for (int j = 0; j < 4; j++) {
                    uint4 B = *(const uint4*)(bp + j * 8);
                    mma_f16(acc[0][2 * j],     a[0], B.x, B.y);
                    mma_f16(acc[1][2 * j],     a[1], B.x, B.y);
                    mma_f16(acc[0][2 * j + 1], a[0], B.z, B.w);
                    mma_f16(acc[1][2 * j + 1], a[1], B.z, B.w);
                }
            }
        }
        __syncthreads();   // all A-reads of h done before epilogue writes

        if (l < 3) {
            // ---- epilogue: bias + FiLM + gelu -> fp16, write back permuted ----
#pragma unroll
            for (int nt = 0; nt < 8; nt++) {
                int n  = n0 + nt * 8 + 2 * cq;
                int pp = (n >> 4) * 16 + cq * 4 + 2 * (nt & 1);
                float g0 = gam_s[n],  g1 = gam_s[n + 1];
                float e0 = bet_s[n],  e1 = bet_s[n + 1];
                float i0 = bias_s[l * HID + n], i1 = bias_s[l * HID + n + 1];
#pragma unroll
                for (int mt = 0; mt < 2; mt++) {
                    int p0 = m0 + mt * 16 + r;
                    *(__half2*)(h_s + p0 * HSH + pp) = __floats2half2_rn(
                        gelu_f((acc[mt][nt][0] + i0) * g0 + e0),
                        gelu_f((acc[mt][nt][1] + i1) * g1 + e1));
                    *(__half2*)(h_s + (p0 + 8) * HSH + pp) = __floats2half2_rn(
                        gelu_f((acc[mt][nt][2] + i0) * g0 + e0),
                        gelu_f((acc[mt][nt][3] + i1) * g1 + e1));
                }
            }
            __syncthreads();
        } else {
            // ---- fused output head: gelu in regs -> xWout -> reduce ----
            float po[12];
#pragma unroll
            for (int i = 0; i < 12; i++) po[i] = 0.f;
#pragma unroll
            for (int nt = 0; nt < 8; nt++) {
                int n  = n0 + nt * 8 + 2 * cq;
                float g0c = gam_s[n],  g1c = gam_s[n + 1];
                float e0 = bet_s[n],   e1 = bet_s[n + 1];
                float i0 = bias_s[3 * HID + n], i1 = bias_s[3 * HID + n + 1];
                float w00 = wo_s[n * 3 + 0], w01 = wo_s[n * 3 + 1], w02 = wo_s[n * 3 + 2];
                float w10 = wo_s[n * 3 + 3], w11 = wo_s[n * 3 + 4], w12 = wo_s[n * 3 + 5];
#pragma unroll
                for (int mt = 0; mt < 2; mt++) {
                    float ga = gelu_f((acc[mt][nt][0] + i0) * g0c + e0);
                    float gb = gelu_f((acc[mt][nt][1] + i1) * g1c + e1);
                    float gc = gelu_f((acc[mt][nt][2] + i0) * g0c + e0);
                    float gd = gelu_f((acc[mt][nt][3] + i1) * g1c + e1);
                    int ix = mt * 6;
                    po[ix + 0] += ga * w00 + gb * w10;
                    po[ix + 1] += ga * w01 + gb * w11;
                    po[ix + 2] += ga * w02 + gb * w12;
                    po[ix + 3] += gc * w00 + gd * w10;
                    po[ix + 4] += gc * w01 + gd * w11;
                    po[ix + 5] += gc * w02 + gd * w12;
                }
            }
            // reduce across the 4 cq lanes (lane bits 0-1)
#pragma unroll
            for (int i = 0; i < 12; i++) {
                po[i] += __shfl_xor_sync(0xffffffffu, po[i], 1);
                po[i] += __shfl_xor_sync(0xffffffffu, po[i], 2);
            }
            if (cq == 0) {
#pragma unroll
                for (int mt = 0; mt < 2; mt++)
#pragma unroll
                    for (int hh = 0; hh < 2; hh++) {
                        int p = m0 + mt * 16 + hh * 8 + r;
                        float* dst = red_s + (p * 4 + nw) * 3;
                        dst[0] = po[mt * 6 + hh * 3 + 0];
                        dst[1] = po[mt * 6 + hh * 3 + 1];
                        dst[2] = po[mt * 6 + hh * 3 + 2];
                    }
            }
            __syncthreads();
            if (tid < 192) {
                int p = tid & 63, o = tid >> 6;
                const float* q4 = red_s + p * 12 + o;
                float acc2 = bo_s[o] + (q4[0] + q4[3]) + (q4[6] + q4[9]);
                out[((size_t)b * NPTS + n0p + p) * 3 + o] = tanh_fast(acc2);
            }
        }
    }
}

// ---------------- launch ----------------
extern "C" void kernel_launch(void* const* d_in, const int* in_sizes, int n_in,
                              void* d_out, int out_size) {
    const float* fg = (const float*)d_in[0];
    const float* cv = (const float*)d_in[1];
    const float* co = (const float*)d_in[2];
    const float* Wc = (const float*)d_in[3];
    const float* bc = (const float*)d_in[4];
    const float* W0 = (const float*)d_in[5];
    const float* b0 = (const float*)d_in[6];
    const float* W1 = (const float*)d_in[7];
    const float* b1 = (const float*)d_in[8];
    const float* W2 = (const float*)d_in[9];
    const float* b2 = (const float*)d_in[10];
    const float* W3 = (const float*)d_in[11];
    const float* b3 = (const float*)d_in[12];
    const float* Wo = (const float*)d_in[13];
    const float* bo = (const float*)d_in[14];
    float* out = (float*)d_out;

    const int smemB = (2 * CHUNKH + TILE_M * HSH) * 2 +
                      (4 * HID + HID + HID + 3 * HID + 4 + 64 * 12) * 4;
    cudaFuncSetAttribute(decoder_kernel,
                         cudaFuncAttributeMaxDynamicSharedMemorySize, smemB);

    prep_all_kernel<<<3912, 256>>>(fg, cv, Wc, bc, W0, W1, W2, W3);
    decoder_kernel<<<BATCH * (NPTS / TILE_M), THREADS, smemB>>>(
        fg, co, b0, b1, b2, b3, Wo, bo, out);
}

// round 12
// speedup vs baseline: 1.1918x; 1.0736x over previous
#include <cuda_runtime.h>
#include <cuda_fp16.h>
#include <cstdint>

#define BATCH    8
#define GH       64
#define C0       64
#define NPTS     16384
#define NFREQ    10
#define HID      256
#define TILE_M   64
#define THREADS  256
#define HSH      288                 // halves per h row (144 words == 16 mod 32)
#define CHUNKH   10752               // halves per 32-k weight chunk (incl pads)

// ---------------- device scratch (static, allocation-free) ----------------
__device__ float  g_gamma[BATCH * HID];
__device__ float  g_beta [BATCH * HID];
__device__ __half g_WT   [4 * 8 * CHUNKH];   // fragment-packed fp16 weights
__device__ float  g_lvl1 [BATCH * 32 * 32 * C0];
__device__ float  g_lvl2 [BATCH * 16 * 16 * C0];

// ---------------- helpers ----------------
__device__ __forceinline__ uint32_t smem_u32(const void* p) {
    uint32_t a;
    asm("{ .reg .u64 t; cvta.to.shared.u64 t, %1; cvt.u32.u64 %0, t; }" : "=r"(a) : "l"(p));
    return a;
}
__device__ __forceinline__ float tanh_fast(float y) {     // accurate (output stage)
    float e; asm("ex2.approx.f32 %0, %1;" : "=f"(e) : "f"(y * 2.8853900817779268f));
    float r; asm("rcp.approx.f32 %0, %1;" : "=f"(r) : "f"(e + 1.0f));
    return 1.0f - 2.0f * r;
}
__device__ __forceinline__ float tanh_hw(float x) {       // 1-MUFU approx (hidden layers)
    float r; asm("tanh.approx.f32 %0, %1;" : "=f"(r) : "f"(x)); return r;
}
__device__ __forceinline__ float gelu_f(float x) {
    float u = 0.7978845608028654f * fmaf(0.044715f * x, x * x, x);
    return 0.5f * x * (1.0f + tanh_hw(u));
}
__device__ __forceinline__ void cp16(uint32_t saddr, const void* g) {
    asm volatile("cp.async.cg.shared.global [%0], [%1], 16;" :: "r"(saddr), "l"(g));
}
__device__ __forceinline__ void mma_f16(float* d, const uint32_t* a,
                                        uint32_t b0, uint32_t b1) {
    asm volatile(
        "mma.sync.aligned.m16n8k16.row.col.f32.f16.f16.f32 "
        "{%0,%1,%2,%3}, {%4,%5,%6,%7}, {%8,%9}, {%0,%1,%2,%3};"
        : "+f"(d[0]), "+f"(d[1]), "+f"(d[2]), "+f"(d[3])
        : "r"(a[0]), "r"(a[1]), "r"(a[2]), "r"(a[3]), "r"(b0), "r"(b1));
}
// chunk-contiguous k-permutation: within each 32-block, thread cq=(k&7)>>1 owns
// 8 contiguous halves: pos = cq*8 + s*4 + b1*2 + b0  (s=k bit4, b1=k bit3, b0=k bit0)
__device__ __host__ __forceinline__ int posf(int k) {
    return (k & ~31) | (((k >> 1) & 3) << 3) | (((k >> 4) & 1) << 2)
         | (((k >> 3) & 1) << 1) | (k & 1);
}

// ================== merged prep (one launch) ==================
// blocks [0,2048): resize lvl1 (HL=32); [2048,2560): resize lvl2 (HL=16);
// [2560,3904): weight pack; [3904,3912): FiLM ctx.

template <int HL>
__device__ void resize_body(int bid, int tid, const float* __restrict__ src) {
    int idx = bid * 256 + tid;
    int c = idx & (C0 - 1);
    int v = idx >> 6;
    int x = v % HL;
    int y = (v / HL) % HL;
    int b = v / (HL * HL);

    const float scale = (float)(GH / HL);
    const int   T     = 2 * (GH / HL);

    float sy = (y + 0.5f) * scale - 0.5f;
    float sx = (x + 0.5f) * scale - 0.5f;
    int s0y = (int)floorf(sy - scale) + 1;
    int s0x = (int)floorf(sx - scale) + 1;

    float wy[8], wx[8];
    float sumy = 0.f, sumx = 0.f;
#pragma unroll
    for (int t = 0; t < T; t++) {
        int s = s0y + t;
        float w = 1.0f - fabsf((float)s - sy) / scale;
        w = (s >= 0 && s < GH && w > 0.f) ? w : 0.f;
        wy[t] = w; sumy += w;
        s = s0x + t;
        w = 1.0f - fabsf((float)s - sx) / scale;
        w = (s >= 0 && s < GH && w > 0.f) ? w : 0.f;
        wx[t] = w; sumx += w;
    }
    float inv = 1.0f / (sumy * sumx);

    float acc = 0.f;
#pragma unroll
    for (int a = 0; a < T; a++) {
        if (wy[a] == 0.f) continue;
        const float* row = src + ((((b * GH) + (s0y + a)) * GH) << 6) + c;
        float pacc = 0.f;
#pragma unroll
        for (int t = 0; t < T; t++) {
            if (wx[t] == 0.f) continue;
            pacc += wx[t] * row[(s0x + t) << 6];
        }
        acc += wy[a] * pacc;
    }
    float* dst = (HL == 32) ? g_lvl1 : g_lvl2;
    dst[idx] = acc * inv;
}

__device__ void prep_wt_body(int bid, int tid,
                             const float* __restrict__ W0,
                             const float* __restrict__ W1,
                             const float* __restrict__ W2,
                             const float* __restrict__ W3) {
    int idx = bid * 256 + tid;                 // 4 * 8 * CHUNKH
    int l   = idx / (8 * CHUNKH);
    int rem = idx % (8 * CHUNKH);
    int c   = rem / CHUNKH;  rem %= CHUNKH;
    int nw  = rem / 2688;    rem %= 2688;
    int s   = rem / 1344;    rem %= 1344;
    int cq  = rem / 336;     rem %= 336;
    float v = 0.0f;
    if (rem < 320) {
        int r   = rem / 40;
        int pos = rem % 40;
        if (pos < 32) {
            int nt = pos >> 2, q = pos & 3;
            int k  = c * 32 + s * 16 + 2 * cq + (q & 1) + ((q >> 1) << 3);
            int n  = nw * 64 + nt * 8 + r;
            if (l == 0) {
                if (k < 42)                  v = W0[k * HID + n];
                else if (k >= 44 && k < 236) v = W0[(k - 2) * HID + n];
            } else if (l == 1) v = W1[k * HID + n];
            else if (l == 2)   v = W2[k * HID + n];
            else               v = W3[k * HID + n];
        }
    }
    g_WT[idx] = __float2half_rn(v);
}

__device__ void prep_ctx_body(int b, int c,
                              const float* __restrict__ cv,
                              const float* __restrict__ Wc,
                              const float* __restrict__ bc) {
    float g  = bc[c];
    float bt = bc[HID + c];
#pragma unroll 8
    for (int k = 0; k < C0; k++) {
        float v = cv[b * C0 + k];
        g  += v * Wc[k * 2 * HID + c];
        bt += v * Wc[k * 2 * HID + HID + c];
    }
    g_gamma[b * HID + c] = g + 1.0f;
    g_beta [b * HID + c] = bt;
}

__global__ void prep_all_kernel(const float* __restrict__ fg,
                                const float* __restrict__ cv,
                                const float* __restrict__ Wc,
                                const float* __restrict__ bc,
                                const float* __restrict__ W0,
                                const float* __restrict__ W1,
                                const float* __restrict__ W2,
                                const float* __restrict__ W3) {
    int bid = blockIdx.x, tid = threadIdx.x;
    if (bid < 2048)       resize_body<32>(bid, tid, fg);
    else if (bid < 2560)  resize_body<16>(bid - 2048, tid, fg);
    else if (bid < 3904)  prep_wt_body(bid - 2560, tid, W0, W1, W2, W3);
    else                  prep_ctx_body(bid - 3904, tid, cv, Wc, bc);
}

// ---------------- weight chunk fill: linear 21 KB copy (256 threads) -------
__device__ __forceinline__ void fill_chunk(__half* wsm, const __half* wt_l,
                                           int c, int tid) {
    uint32_t sb = smem_u32(wsm);
    const char* src = (const char*)(wt_l + c * CHUNKH);
#pragma unroll
    for (int s = 0; s < 5; s++) {
        int u = tid + s * THREADS;          // 16B units, 1344 total
        cp16(sb + u * 16, src + (size_t)u * 16);
    }
    if (tid < 64) { int u = 1280 + tid; cp16(sb + u * 16, src + (size_t)u * 16); }
    asm volatile("cp.async.commit_group;" ::: "memory");
}

// ---------------- main fused decoder (mma.sync fp16, 2 CTAs/SM) ------------
__global__ __launch_bounds__(THREADS, 2)
void decoder_kernel(const float* __restrict__ fg,
                    const float* __restrict__ coords,
                    const float* __restrict__ b0, const float* __restrict__ b1,
                    const float* __restrict__ b2, const float* __restrict__ b3,
                    const float* __restrict__ Wout, const float* __restrict__ bout,
                    float* __restrict__ out) {
    extern __shared__ char smem_raw[];
    __half* wbuf   = (__half*)smem_raw;                       // 2 * CHUNKH
    __half* h_s    = wbuf + 2 * CHUNKH;                       // 64 * 288
    float*  bias_s = (float*)(h_s + TILE_M * HSH);            // 4*256
    float*  gam_s  = bias_s + 4 * HID;
    float*  bet_s  = gam_s + HID;
    float*  wo_s   = bet_s + HID;                             // 3*256, straight [n][o]
    float*  bo_s   = wo_s + 3 * HID;                          // 4
    float*  red_s  = bo_s + 4;                                // 64*4*3

    const int tid  = threadIdx.x;
    const int lane = tid & 31;
    const int wid  = tid >> 5;
    const int mw   = wid & 1,  nw = wid >> 1;
    const int m0   = mw * 32,  n0 = nw * 64;
    const int r    = lane >> 2, cq = lane & 3;
    const int b    = blockIdx.x >> 8;
    const int n0p  = (blockIdx.x & 255) * TILE_M;

    // prefill layer-0 chunk 0 (overlaps feature build)
    fill_chunk(wbuf, g_WT, 0, tid);

    // stage per-CTA params
    gam_s[tid]  = g_gamma[b * HID + tid];
    bet_s[tid]  = g_beta [b * HID + tid];
    bias_s[tid]           = b0[tid];
    bias_s[HID + tid]     = b1[tid];
    bias_s[2 * HID + tid] = b2[tid];
    bias_s[3 * HID + tid] = b3[tid];
    for (int j = tid; j < 3 * HID; j += THREADS) wo_s[j] = Wout[j];
    if (tid < 3) bo_s[tid] = bout[tid];

    // ---- build features (fp16, posf-permuted k): 4 threads per point ----
    {
        int p = tid >> 2, q = tid & 3;
        float cy = coords[(n0p + p) * 2 + 0];
        float cx = coords[(n0p + p) * 2 + 1];
        __half* hp = h_s + p * HSH;

        if (q == 0) {
            hp[posf(0)] = __float2half_rn(cy);
            hp[posf(1)] = __float2half_rn(cx);
            float fr = 3.14159265358979323846f;
#pragma unroll
            for (int f = 0; f < NFREQ; f++) {
                float sv, cvv;
                sincosf(cy * fr, &sv, &cvv);
                hp[posf(2 + 4 * f + 0)] = __float2half_rn(sv);
                hp[posf(2 + 4 * f + 2)] = __float2half_rn(cvv);
                sincosf(cx * fr, &sv, &cvv);
                hp[posf(2 + 4 * f + 1)] = __float2half_rn(sv);
                hp[posf(2 + 4 * f + 3)] = __float2half_rn(cvv);
                fr *= 2.0f;
            }
            hp[posf(42)] = __float2half_rn(0.f);
            hp[posf(43)] = __float2half_rn(0.f);
#pragma unroll
            for (int k = 236; k < 256; k++) hp[posf(k)] = __float2half_rn(0.f);
        }

#pragma unroll
        for (int lvl = 0; lvl < 3; lvl++) {
            int Hl = GH >> lvl;
            const float* G = (lvl == 0) ? fg : ((lvl == 1) ? g_lvl1 : g_lvl2);
            float yf = (cy + 1.0f) * 0.5f * (float)(Hl - 1);
            float xf = (cx + 1.0f) * 0.5f * (float)(Hl - 1);
            float y0f = floorf(yf), x0f = floorf(xf);
            float wy = yf - y0f, wx = xf - x0f;
            int y0 = min(max((int)y0f, 0), Hl - 1);
            int x0 = min(max((int)x0f, 0), Hl - 1);
            int y1 = min(y0 + 1, Hl - 1);
            int x1 = min(x0 + 1, Hl - 1);
            const float* p00 = G + ((((b * Hl) + y0) * Hl + x0) << 6);
            const float* p01 = G + ((((b * Hl) + y0) * Hl + x1) << 6);
            const float* p10 = G + ((((b * Hl) + y1) * Hl + x0) << 6);
            const float* p11 = G + ((((b * Hl) + y1) * Hl + x1) << 6);
            float omx = 1.0f - wx, omy = 1.0f - wy;
            int base = 44 + lvl * 64 + q * 16;
#pragma unroll
            for (int cc = 0; cc < 4; cc++) {
                int c = q * 16 + cc * 4;
                float4 v00 = *(const float4*)(p00 + c);
                float4 v01 = *(const float4*)(p01 + c);
                float4 v10 = *(const float4*)(p10 + c);
                float4 v11 = *(const float4*)(p11 + c);
                hp[posf(base + cc * 4 + 0)] = __float2half_rn(
                    (v00.x * omx + v01.x * wx) * omy + (v10.x * omx + v11.x * wx) * wy);
                hp[posf(base + cc * 4 + 1)] = __float2half_rn(
                    (v00.y * omx + v01.y * wx) * omy + (v10.y * omx + v11.y * wx) * wy);
                hp[posf(base + cc * 4 + 2)] = __float2half_rn(
                    (v00.z * omx + v01.z * wx) * omy + (v10.z * omx + v11.z * wx) * wy);
                hp[posf(base + cc * 4 + 3)] = __float2half_rn(
                    (v00.w * omx + v01.w * wx) * omy + (v10.w * omx + v11.w * wx) * wy);
            }
        }
    }

    // ---- 4 FiLM'd MLP layers on tensor cores (fp16 m16n8k16) ----
    for (int l = 0; l < 4; l++) {
        const __half* WTl = g_WT + l * (8 * CHUNKH);

        float acc[2][8][4];
#pragma unroll
        for (int i = 0; i < 2; i++)
#pragma unroll
            for (int j = 0; j < 8; j++)
#pragma unroll
                for (int v = 0; v < 4; v++) acc[i][j][v] = 0.f;

#pragma unroll
        for (int c = 0; c < 8; c++) {
            asm volatile("cp.async.wait_group 0;" ::: "memory");
            __syncthreads();
            if (c < 7)      fill_chunk(wbuf + ((c + 1) & 1) * CHUNKH, WTl, c + 1, tid);
            else if (l < 3) fill_chunk(wbuf + ((c + 1) & 1) * CHUNKH,
                                       g_WT + (l + 1) * (8 * CHUNKH), 0, tid);

            const __half* wb = wbuf + (c & 1) * CHUNKH + nw * 2688;

            // A: one LDS.128 per (mt,row-half) covers the whole 32-k chunk
            uint32_t a[2][2][4];     // [s][mt][frag]
#pragma unroll
            for (int mt = 0; mt < 2; mt++) {
                int row = m0 + mt * 16 + r;
                const char* h0 = (const char*)(h_s + row * HSH) + c * 64 + cq * 16;
                const char* h1 = (const char*)(h_s + (row + 8) * HSH) + c * 64 + cq * 16;
                uint4 A0 = *(const uint4*)h0;
                uint4 A1 = *(const uint4*)h1;
                a[0][mt][0] = A0.x; a[0][mt][1] = A1.x;
                a[0][mt][2] = A0.y; a[0][mt][3] = A1.y;
                a[1][mt][0] = A0.z; a[1][mt][1] = A1.z;
                a[1][mt][2] = A0.w; a[1][mt][3] = A1.w;
            }
#pragma unroll
            for (int s = 0; s < 2; s++) {
                const __half* bp = wb + s * 1344 + cq * 336 + r * 40;
#pragma unroll
                for (int j = 0; j < 4; j++) {
                    uint4 B = *(const uint4*)(bp + j * 8);
                    mma_f16(acc[0][2 * j],     a[s][0], B.x, B.y);
                    mma_f16(acc[1][2 * j],     a[s][1], B.x, B.y);
                    mma_f16(acc[0][2 * j + 1], a[s][0], B.z, B.w);
                    mma_f16(acc[1][2 * j + 1], a[s][1], B.z, B.w);
                }
            }
        }
        __syncthreads();   // all A-reads of h done before epilogue writes

        if (l < 3) {
            // ---- epilogue: bias + FiLM + gelu -> fp16, write back permuted ----
#pragma unroll
            for (int nt = 0; nt < 8; nt++) {
                int n  = n0 + nt * 8 + 2 * cq;
                int pp = (n & ~31) | (cq << 3) | (((n >> 4) & 1) << 2)
                       | (((n >> 3) & 1) << 1);
                float g0 = gam_s[n],  g1 = gam_s[n + 1];
                float e0 = bet_s[n],  e1 = bet_s[n + 1];
                float i0 = bias_s[l * HID + n], i1 = bias_s[l * HID + n + 1];
#pragma unroll
                for (int mt = 0; mt < 2; mt++) {
                    int p0 = m0 + mt * 16 + r;
                    *(__half2*)(h_s + p0 * HSH + pp) = __floats2half2_rn(
                        gelu_f((acc[mt][nt][0] + i0) * g0 + e0),
                        gelu_f((acc[mt][nt][1] + i1) * g1 + e1));
                    *(__half2*)(h_s + (p0 + 8) * HSH + pp) = __floats2half2_rn(
                        gelu_f((acc[mt][nt][2] + i0) * g0 + e0),
                        gelu_f((acc[mt][nt][3] + i1) * g1 + e1));
                }
            }
            __syncthreads();
        } else {
            // ---- fused output head: gelu in regs -> xWout -> reduce ----
            float po[12];
#pragma unroll
            for (int i = 0; i < 12; i++) po[i] = 0.f;
#pragma unroll
            for (int nt = 0; nt < 8; nt++) {
                int n  = n0 + nt * 8 + 2 * cq;
                float g0c = gam_s[n],  g1c = gam_s[n + 1];
                float e0 = bet_s[n],   e1 = bet_s[n + 1];
                float i0 = bias_s[3 * HID + n], i1 = bias_s[3 * HID + n + 1];
                float w00 = wo_s[n * 3 + 0], w01 = wo_s[n * 3 + 1], w02 = wo_s[n * 3 + 2];
                float w10 = wo_s[n * 3 + 3], w11 = wo_s[n * 3 + 4], w12 = wo_s[n * 3 + 5];
#pragma unroll
                for (int mt = 0; mt < 2; mt++) {
                    float ga = gelu_f((acc[mt][nt][0] + i0) * g0c + e0);
                    float gb = gelu_f((acc[mt][nt][1] + i1) * g1c + e1);
                    float gc = gelu_f((acc[mt][nt][2] + i0) * g0c + e0);
                    float gd = gelu_f((acc[mt][nt][3] + i1) * g1c + e1);
                    int ix = mt * 6;
                    po[ix + 0] += ga * w00 + gb * w10;
                    po[ix + 1] += ga * w01 + gb * w11;
                    po[ix + 2] += ga * w02 + gb * w12;
                    po[ix + 3] += gc * w00 + gd * w10;
                    po[ix + 4] += gc * w01 + gd * w11;
                    po[ix + 5] += gc * w02 + gd * w12;
                }
            }
            // reduce across the 4 cq lanes (lane bits 0-1)
#pragma unroll
            for (int i = 0; i < 12; i++) {
                po[i] += __shfl_xor_sync(0xffffffffu, po[i], 1);
                po[i] += __shfl_xor_sync(0xffffffffu, po[i], 2);
            }
            if (cq == 0) {
#pragma unroll
                for (int mt = 0; mt < 2; mt++)
#pragma unroll
                    for (int hh = 0; hh < 2; hh++) {
                        int p = m0 + mt * 16 + hh * 8 + r;
                        float* dst = red_s + (p * 4 + nw) * 3;
                        dst[0] = po[mt * 6 + hh * 3 + 0];
                        dst[1] = po[mt * 6 + hh * 3 + 1];
                        dst[2] = po[mt * 6 + hh * 3 + 2];
                    }
            }
            __syncthreads();
            if (tid < 192) {
                int p = tid & 63, o = tid >> 6;
                const float* q4 = red_s + p * 12 + o;
                float acc2 = bo_s[o] + (q4[0] + q4[3]) + (q4[6] + q4[9]);
                out[((size_t)b * NPTS + n0p + p) * 3 + o] = tanh_fast(acc2);
            }
        }
    }
}

// ---------------- launch ----------------
extern "C" void kernel_launch(void* const* d_in, const int* in_sizes, int n_in,
                              void* d_out, int out_size) {
    const float* fg = (const float*)d_in[0];
    const float* cv = (const float*)d_in[1];
    const float* co = (const float*)d_in[2];
    const float* Wc = (const float*)d_in[3];
    const float* bc = (const float*)d_in[4];
    const float* W0 = (const float*)d_in[5];
    const float* b0 = (const float*)d_in[6];
    const float* W1 = (const float*)d_in[7];
    const float* b1 = (const float*)d_in[8];
    const float* W2 = (const float*)d_in[9];
    const float* b2 = (const float*)d_in[10];
    const float* W3 = (const float*)d_in[11];
    const float* b3 = (const float*)d_in[12];
    const float* Wo = (const float*)d_in[13];
    const float* bo = (const float*)d_in[14];
    float* out = (float*)d_out;

    const int smemB = (2 * CHUNKH + TILE_M * HSH) * 2 +
                      (4 * HID + HID + HID + 3 * HID + 4 + 64 * 12) * 4;
    cudaFuncSetAttribute(decoder_kernel,
                         cudaFuncAttributeMaxDynamicSharedMemorySize, smemB);

    prep_all_kernel<<<3912, 256>>>(fg, cv, Wc, bc, W0, W1, W2, W3);
    decoder_kernel<<<BATCH * (NPTS / TILE_M), THREADS, smemB>>>(
        fg, co, b0, b1, b2, b3, Wo, bo, out);
}

// round 13
// speedup vs baseline: 1.3018x; 1.0923x over previous
#include <cuda_runtime.h>
#include <cuda_fp16.h>
#include <cstdint>

#define BATCH    8
#define GH       64
#define C0       64
#define NPTS     16384
#define NFREQ    10
#define HID      256
#define TILE_M   64
#define THREADS  256
#define HSH      288                 // halves per h row (144 words == 16 mod 32)
#define WT_L     65536               // halves per layer (no pads)

// ---------------- device scratch (static, allocation-free) ----------------
__device__ float  g_gamma[BATCH * HID];
__device__ float  g_beta [BATCH * HID];
__device__ __half g_WT   [4 * WT_L];         // coalesced fragment-packed fp16 weights
__device__ float  g_lvl1 [BATCH * 32 * 32 * C0];
__device__ float  g_lvl2 [BATCH * 16 * 16 * C0];

// ---------------- helpers ----------------
__device__ __forceinline__ float tanh_fast(float y) {     // accurate (output stage)
    float e; asm("ex2.approx.f32 %0, %1;" : "=f"(e) : "f"(y * 2.8853900817779268f));
    float r; asm("rcp.approx.f32 %0, %1;" : "=f"(r) : "f"(e + 1.0f));
    return 1.0f - 2.0f * r;
}
__device__ __forceinline__ float tanh_hw(float x) {       // 1-MUFU approx (hidden layers)
    float r; asm("tanh.approx.f32 %0, %1;" : "=f"(r) : "f"(x)); return r;
}
__device__ __forceinline__ float gelu_f(float x) {
    float u = 0.7978845608028654f * fmaf(0.044715f * x, x * x, x);
    return 0.5f * x * (1.0f + tanh_hw(u));
}
__device__ __forceinline__ void mma_f16(float* d, const uint32_t* a,
                                        uint32_t b0, uint32_t b1) {
    asm volatile(
        "mma.sync.aligned.m16n8k16.row.col.f32.f16.f16.f32 "
        "{%0,%1,%2,%3}, {%4,%5,%6,%7}, {%8,%9}, {%0,%1,%2,%3};"
        : "+f"(d[0]), "+f"(d[1]), "+f"(d[2]), "+f"(d[3])
        : "r"(a[0]), "r"(a[1]), "r"(a[2]), "r"(a[3]), "r"(b0), "r"(b1));
}
// chunk-contiguous k-permutation: within each 32-block, thread cq=(k&7)>>1 owns
// 8 contiguous halves: pos = cq*8 + s*4 + b1*2 + b0  (s=k bit4, b1=k bit3, b0=k bit0)
__device__ __host__ __forceinline__ int posf(int k) {
    return (k & ~31) | (((k >> 1) & 3) << 3) | (((k >> 4) & 1) << 2)
         | (((k >> 3) & 1) << 1) | (k & 1);
}

// ================== merged prep (one launch) ==================
// blocks [0,2048): resize lvl1; [2048,2560): resize lvl2; [2560,3584): weight
// pack; [3584,3592): FiLM ctx.

template <int HL>
__device__ void resize_body(int bid, int tid, const float* __restrict__ src) {
    int idx = bid * 256 + tid;
    int c = idx & (C0 - 1);
    int v = idx >> 6;
    int x = v % HL;
    int y = (v / HL) % HL;
    int b = v / (HL * HL);

    const float scale = (float)(GH / HL);
    const int   T     = 2 * (GH / HL);

    float sy = (y + 0.5f) * scale - 0.5f;
    float sx = (x + 0.5f) * scale - 0.5f;
    int s0y = (int)floorf(sy - scale) + 1;
    int s0x = (int)floorf(sx - scale) + 1;

    float wy[8], wx[8];
    float sumy = 0.f, sumx = 0.f;
#pragma unroll
    for (int t = 0; t < T; t++) {
        int s = s0y + t;
        float w = 1.0f - fabsf((float)s - sy) / scale;
        w = (s >= 0 && s < GH && w > 0.f) ? w : 0.f;
        wy[t] = w; sumy += w;
        s = s0x + t;
        w = 1.0f - fabsf((float)s - sx) / scale;
        w = (s >= 0 && s < GH && w > 0.f) ? w : 0.f;
        wx[t] = w; sumx += w;
    }
    float inv = 1.0f / (sumy * sumx);

    float acc = 0.f;
#pragma unroll
    for (int a = 0; a < T; a++) {
        if (wy[a] == 0.f) continue;
        const float* row = src + ((((b * GH) + (s0y + a)) * GH) << 6) + c;
        float pacc = 0.f;
#pragma unroll
        for (int t = 0; t < T; t++) {
            if (wx[t] == 0.f) continue;
            pacc += wx[t] * row[(s0x + t) << 6];
        }
        acc += wy[a] * pacc;
    }
    float* dst = (HL == 32) ? g_lvl1 : g_lvl2;
    dst[idx] = acc * inv;
}

// Weight pack, coalesced LDG layout (halves):
//   idx = [l:2][c:3][nw:2][s:1][j:2][lane:5][u:3]
//   value = W[k][n] with k = c*32 + s*16 + 2*cq + (u&1) + (((u>>1)&1)<<3),
//   n = nw*64 + (2*j + (u>>2))*8 + r   (lane = r*4+cq)
// layer-0 K remap: [0..41]->rows 0..41, [42..43] zero, [44..235]->rows 42..233,
// [236..255] zero (matches the h-tile posf layout).
__device__ void prep_wt_body(int bid, int tid,
                             const float* __restrict__ W0,
                             const float* __restrict__ W1,
                             const float* __restrict__ W2,
                             const float* __restrict__ W3) {
    int idx  = bid * 256 + tid;                // 4 * WT_L
    int u    = idx & 7;
    int lane = (idx >> 3) & 31;
    int j    = (idx >> 8) & 3;
    int s    = (idx >> 10) & 1;
    int nw   = (idx >> 11) & 3;
    int c    = (idx >> 13) & 7;
    int l    = idx >> 16;
    int r = lane >> 2, cq = lane & 3;
    int nt = 2 * j + (u >> 2);
    int q  = u & 3;
    int k = c * 32 + s * 16 + 2 * cq + (q & 1) + ((q >> 1) << 3);
    int n = nw * 64 + nt * 8 + r;
    float v = 0.0f;
    if (l == 0) {
        if (k < 42)                  v = W0[k * HID + n];
        else if (k >= 44 && k < 236) v = W0[(k - 2) * HID + n];
    } else if (l == 1) v = W1[k * HID + n];
    else if (l == 2)   v = W2[k * HID + n];
    else               v = W3[k * HID + n];
    g_WT[idx] = __float2half_rn(v);
}

__device__ void prep_ctx_body(int b, int c,
                              const float* __restrict__ cv,
                              const float* __restrict__ Wc,
                              const float* __restrict__ bc) {
    float g  = bc[c];
    float bt = bc[HID + c];
#pragma unroll 8
    for (int k = 0; k < C0; k++) {
        float v = cv[b * C0 + k];
        g  += v * Wc[k * 2 * HID + c];
        bt += v * Wc[k * 2 * HID + HID + c];
    }
    g_gamma[b * HID + c] = g + 1.0f;
    g_beta [b * HID + c] = bt;
}

__global__ void prep_all_kernel(const float* __restrict__ fg,
                                const float* __restrict__ cv,
                                const float* __restrict__ Wc,
                                const float* __restrict__ bc,
                                const float* __restrict__ W0,
                                const float* __restrict__ W1,
                                const float* __restrict__ W2,
                                const float* __restrict__ W3) {
    int bid = blockIdx.x, tid = threadIdx.x;
    if (bid < 2048)       resize_body<32>(bid, tid, fg);
    else if (bid < 2560)  resize_body<16>(bid - 2048, tid, fg);
    else if (bid < 3584)  prep_wt_body(bid - 2560, tid, W0, W1, W2, W3);
    else                  prep_ctx_body(bid - 3584, tid, cv, Wc, bc);
}

// ---------------- main fused decoder (fp16 HMMA, direct-LDG weights) -------
__global__ __launch_bounds__(THREADS, 2)
void decoder_kernel(const float* __restrict__ fg,
                    const float* __restrict__ coords,
                    const float* __restrict__ b0, const float* __restrict__ b1,
                    const float* __restrict__ b2, const float* __restrict__ b3,
                    const float* __restrict__ Wout, const float* __restrict__ bout,
                    float* __restrict__ out) {
    extern __shared__ char smem_raw[];
    __half* h_s    = (__half*)smem_raw;                       // 64 * 288
    float*  bias_s = (float*)(h_s + TILE_M * HSH);            // 4*256
    float*  gam_s  = bias_s + 4 * HID;
    float*  bet_s  = gam_s + HID;
    float*  wo_s   = bet_s + HID;                             // 3*256, straight [n][o]
    float*  bo_s   = wo_s + 3 * HID;                          // 4
    float*  red_s  = bo_s + 4;                                // 64*4*3

    const int tid  = threadIdx.x;
    const int lane = tid & 31;
    const int wid  = tid >> 5;
    const int mw   = wid & 1,  nw = wid >> 1;
    const int m0   = mw * 32,  n0 = nw * 64;
    const int r    = lane >> 2, cq = lane & 3;
    const int b    = blockIdx.x >> 8;
    const int n0p  = (blockIdx.x & 255) * TILE_M;

    // per-warp weight base (uint4 granularity, coalesced: +lane)
    const int woff = nw * 2048;          // halves within a chunk block

    // B register double buffer; prologue: load (layer0, chunk0, s0) early
    uint4 Bb[2][4];
    {
        const uint4* p = (const uint4*)(g_WT + woff) + lane;
        Bb[0][0] = p[0]; Bb[0][1] = p[32]; Bb[0][2] = p[64]; Bb[0][3] = p[96];
    }

    // stage per-CTA params
    gam_s[tid]  = g_gamma[b * HID + tid];
    bet_s[tid]  = g_beta [b * HID + tid];
    bias_s[tid]           = b0[tid];
    bias_s[HID + tid]     = b1[tid];
    bias_s[2 * HID + tid] = b2[tid];
    bias_s[3 * HID + tid] = b3[tid];
    for (int j = tid; j < 3 * HID; j += THREADS) wo_s[j] = Wout[j];
    if (tid < 3) bo_s[tid] = bout[tid];

    // ---- build features (fp16, posf-permuted k): 4 threads per point ----
    {
        int p = tid >> 2, q = tid & 3;
        float cy = coords[(n0p + p) * 2 + 0];
        float cx = coords[(n0p + p) * 2 + 1];
        __half* hp = h_s + p * HSH;

        if (q == 0) {
            hp[posf(0)] = __float2half_rn(cy);
            hp[posf(1)] = __float2half_rn(cx);
            float fr = 3.14159265358979323846f;
#pragma unroll
            for (int f = 0; f < NFREQ; f++) {
                float sv, cvv;
                sincosf(cy * fr, &sv, &cvv);
                hp[posf(2 + 4 * f + 0)] = __float2half_rn(sv);
                hp[posf(2 + 4 * f + 2)] = __float2half_rn(cvv);
                sincosf(cx * fr, &sv, &cvv);
                hp[posf(2 + 4 * f + 1)] = __float2half_rn(sv);
                hp[posf(2 + 4 * f + 3)] = __float2half_rn(cvv);
                fr *= 2.0f;
            }
            hp[posf(42)] = __float2half_rn(0.f);
            hp[posf(43)] = __float2half_rn(0.f);
#pragma unroll
            for (int k = 236; k < 256; k++) hp[posf(k)] = __float2half_rn(0.f);
        }

#pragma unroll
        for (int lvl = 0; lvl < 3; lvl++) {
            int Hl = GH >> lvl;
            const float* G = (lvl == 0) ? fg : ((lvl == 1) ? g_lvl1 : g_lvl2);
            float yf = (cy + 1.0f) * 0.5f * (float)(Hl - 1);
            float xf = (cx + 1.0f) * 0.5f * (float)(Hl - 1);
            float y0f = floorf(yf), x0f = floorf(xf);
            float wy = yf - y0f, wx = xf - x0f;
            int y0 = min(max((int)y0f, 0), Hl - 1);
            int x0 = min(max((int)x0f, 0), Hl - 1);
            int y1 = min(y0 + 1, Hl - 1);
            int x1 = min(x0 + 1, Hl - 1);
            const float* p00 = G + ((((b * Hl) + y0) * Hl + x0) << 6);
            const float* p01 = G + ((((b * Hl) + y0) * Hl + x1) << 6);
            const float* p10 = G + ((((b * Hl) + y1) * Hl + x0) << 6);
            const float* p11 = G + ((((b * Hl) + y1) * Hl + x1) << 6);
            float omx = 1.0f - wx, omy = 1.0f - wy;
            int base = 44 + lvl * 64 + q * 16;
#pragma unroll
            for (int cc = 0; cc < 4; cc++) {
                int c = q * 16 + cc * 4;
                float4 v00 = *(const float4*)(p00 + c);
                float4 v01 = *(const float4*)(p01 + c);
                float4 v10 = *(const float4*)(p10 + c);
                float4 v11 = *(const float4*)(p11 + c);
                hp[posf(base + cc * 4 + 0)] = __float2half_rn(
                    (v00.x * omx + v01.x * wx) * omy + (v10.x * omx + v11.x * wx) * wy);
                hp[posf(base + cc * 4 + 1)] = __float2half_rn(
                    (v00.y * omx + v01.y * wx) * omy + (v10.y * omx + v11.y * wx) * wy);
                hp[posf(base + cc * 4 + 2)] = __float2half_rn(
                    (v00.z * omx + v01.z * wx) * omy + (v10.z * omx + v11.z * wx) * wy);
                hp[posf(base + cc * 4 + 3)] = __float2half_rn(
                    (v00.w * omx + v01.w * wx) * omy + (v10.w * omx + v11.w * wx) * wy);
            }
        }
    }
    __syncthreads();    // h tile + params visible to all warps

    // ---- 4 FiLM'd MLP layers on tensor cores (fp16 m16n8k16) ----
    for (int l = 0; l < 4; l++) {
        const __half* WTl = g_WT + l * WT_L;

        float acc[2][8][4];
#pragma unroll
        for (int i = 0; i < 2; i++)
#pragma unroll
            for (int j = 0; j < 8; j++)
#pragma unroll
                for (int v = 0; v < 4; v++) acc[i][j][v] = 0.f;

#pragma unroll
        for (int c = 0; c < 8; c++) {
            // A: one LDS.128 per (mt,row-half) covers the whole 32-k chunk
            uint32_t a[2][2][4];     // [s][mt][frag]
#pragma unroll
            for (int mt = 0; mt < 2; mt++) {
                int row = m0 + mt * 16 + r;
                const char* h0 = (const char*)(h_s + row * HSH) + c * 64 + cq * 16;
                const char* h1 = (const char*)(h_s + (row + 8) * HSH) + c * 64 + cq * 16;
                uint4 A0 = *(const uint4*)h0;
                uint4 A1 = *(const uint4*)h1;
                a[0][mt][0] = A0.x; a[0][mt][1] = A1.x;
                a[0][mt][2] = A0.y; a[0][mt][3] = A1.y;
                a[1][mt][0] = A0.z; a[1][mt][1] = A1.z;
                a[1][mt][2] = A0.w; a[1][mt][3] = A1.w;
            }
#pragma unroll
            for (int s = 0; s < 2; s++) {
                const int step = c * 2 + s;
                const int cur  = step & 1;
                // prefetch next half-chunk (or next layer's first) into other buf
                if (step < 15) {
                    int ns = step + 1;
                    const uint4* np = (const uint4*)(WTl + (ns >> 1) * 8192 +
                                                     (ns & 1) * 1024 + woff) + lane;
                    Bb[cur ^ 1][0] = np[0];  Bb[cur ^ 1][1] = np[32];
                    Bb[cur ^ 1][2] = np[64]; Bb[cur ^ 1][3] = np[96];
                } else if (l < 3) {
                    const uint4* np = (const uint4*)(WTl + WT_L + woff) + lane;
                    Bb[cur ^ 1][0] = np[0];  Bb[cur ^ 1][1] = np[32];
                    Bb[cur ^ 1][2] = np[64]; Bb[cur ^ 1][3] = np[96];
                }
#pragma unroll
                for (int j = 0; j < 4; j++) {
                    uint4 B = Bb[cur][j];
                    mma_f16(acc[0][2 * j],     a[s][0], B.x, B.y);
                    mma_f16(acc[1][2 * j],     a[s][1], B.x, B.y);
                    mma_f16(acc[0][2 * j + 1], a[s][0], B.z, B.w);
                    mma_f16(acc[1][2 * j + 1], a[s][1], B.z, B.w);
                }
            }
        }
        __syncthreads();   // all A-reads of h done before epilogue writes

        if (l < 3) {
            // ---- epilogue: bias + FiLM + gelu -> fp16, write back permuted ----
#pragma unroll
            for (int nt = 0; nt < 8; nt++) {
                int n  = n0 + nt * 8 + 2 * cq;
                int pp = (n & ~31) | (cq << 3) | (((n >> 4) & 1) << 2)
                       | (((n >> 3) & 1) << 1);
                float g0 = gam_s[n],  g1 = gam_s[n + 1];
                float e0 = bet_s[n],  e1 = bet_s[n + 1];
                float i0 = bias_s[l * HID + n], i1 = bias_s[l * HID + n + 1];
#pragma unroll
                for (int mt = 0; mt < 2; mt++) {
                    int p0 = m0 + mt * 16 + r;
                    *(__half2*)(h_s + p0 * HSH + pp) = __floats2half2_rn(
                        gelu_f((acc[mt][nt][0] + i0) * g0 + e0),
                        gelu_f((acc[mt][nt][1] + i1) * g1 + e1));
                    *(__half2*)(h_s + (p0 + 8) * HSH + pp) = __floats2half2_rn(
                        gelu_f((acc[mt][nt][2] + i0) * g0 + e0),
                        gelu_f((acc[mt][nt][3] + i1) * g1 + e1));
                }
            }
            __syncthreads();
        } else {
            // ---- fused output head: gelu in regs -> xWout -> reduce ----
            float po[12];
#pragma unroll
            for (int i = 0; i < 12; i++) po[i] = 0.f;
#pragma unroll
            for (int nt = 0; nt < 8; nt++) {
                int n  = n0 + nt * 8 + 2 * cq;
                float g0c = gam_s[n],  g1c = gam_s[n + 1];
                float e0 = bet_s[n],   e1 = bet_s[n + 1];
                float i0 = bias_s[3 * HID + n], i1 = bias_s[3 * HID + n + 1];
                float w00 = wo_s[n * 3 + 0], w01 = wo_s[n * 3 + 1], w02 = wo_s[n * 3 + 2];
                float w10 = wo_s[n * 3 + 3], w11 = wo_s[n * 3 + 4], w12 = wo_s[n * 3 + 5];
#pragma unroll
                for (int mt = 0; mt < 2; mt++) {
                    float ga = gelu_f((acc[mt][nt][0] + i0) * g0c + e0);
                    float gb = gelu_f((acc[mt][nt][1] + i1) * g1c + e1);
                    float gc = gelu_f((acc[mt][nt][2] + i0) * g0c + e0);
                    float gd = gelu_f((acc[mt][nt][3] + i1) * g1c + e1);
                    int ix = mt * 6;
                    po[ix + 0] += ga * w00 + gb * w10;
                    po[ix + 1] += ga * w01 + gb * w11;
                    po[ix + 2] += ga * w02 + gb * w12;
                    po[ix + 3] += gc * w00 + gd * w10;
                    po[ix + 4] += gc * w01 + gd * w11;
                    po[ix + 5] += gc * w02 + gd * w12;
                }
            }
            // reduce across the 4 cq lanes (lane bits 0-1)
#pragma unroll
            for (int i = 0; i < 12; i++) {
                po[i] += __shfl_xor_sync(0xffffffffu, po[i], 1);
                po[i] += __shfl_xor_sync(0xffffffffu, po[i], 2);
            }
            if (cq == 0) {
#pragma unroll
                for (int mt = 0; mt < 2; mt++)
#pragma unroll
                    for (int hh = 0; hh < 2; hh++) {
                        int p = m0 + mt * 16 + hh * 8 + r;
                        float* dst = red_s + (p * 4 + nw) * 3;
                        dst[0] = po[mt * 6 + hh * 3 + 0];
                        dst[1] = po[mt * 6 + hh * 3 + 1];
                        dst[2] = po[mt * 6 + hh * 3 + 2];
                    }
            }
            __syncthreads();
            if (tid < 192) {
                int p = tid & 63, o = tid >> 6;
                const float* q4 = red_s + p * 12 + o;
                float acc2 = bo_s[o] + (q4[0] + q4[3]) + (q4[6] + q4[9]);
                out[((size_t)b * NPTS + n0p + p) * 3 + o] = tanh_fast(acc2);
            }
        }
    }
}

// ---------------- launch ----------------
extern "C" void kernel_launch(void* const* d_in, const int* in_sizes, int n_in,
                              void* d_out, int out_size) {
    const float* fg = (const float*)d_in[0];
    const float* cv = (const float*)d_in[1];
    const float* co = (const float*)d_in[2];
    const float* Wc = (const float*)d_in[3];
    const float* bc = (const float*)d_in[4];
    const float* W0 = (const float*)d_in[5];
    const float* b0 = (const float*)d_in[6];
    const float* W1 = (const float*)d_in[7];
    const float* b1 = (const float*)d_in[8];
    const float* W2 = (const float*)d_in[9];
    const float* b2 = (const float*)d_in[10];
    const float* W3 = (const float*)d_in[11];
    const float* b3 = (const float*)d_in[12];
    const float* Wo = (const float*)d_in[13];
    const float* bo = (const float*)d_in[14];
    float* out = (float*)d_out;

    const int smemB = TILE_M * HSH * 2 +
                      (4 * HID + HID + HID + 3 * HID + 4 + 64 * 12) * 4;
    cudaFuncSetAttribute(decoder_kernel,
                         cudaFuncAttributeMaxDynamicSharedMemorySize, smemB);

    prep_all_kernel<<<3592, 256>>>(fg, cv, Wc, bc, W0, W1, W2, W3);
    decoder_kernel<<<BATCH * (NPTS / TILE_M), THREADS, smemB>>>(
        fg, co, b0, b1, b2, b3, Wo, bo, out);
}

// round 14
// speedup vs baseline: 1.3874x; 1.0657x over previous
#include <cuda_runtime.h>
#include <cuda_fp16.h>
#include <cstdint>

#define BATCH    8
#define GH       64
#define C0       64
#define NPTS     16384
#define NFREQ    10
#define HID      256
#define TILE_M   64
#define THREADS  256
#define HSH      288                 // halves per h row (144 words == 16 mod 32)
#define WT_L     65536               // halves per layer (no pads)

// ---------------- device scratch (static, allocation-free) ----------------
__device__ float  g_gamma[BATCH * HID];
__device__ float  g_beta [BATCH * HID];
__device__ __half g_WT   [4 * WT_L];         // coalesced fragment-packed fp16 weights
__device__ float  g_lvl1 [BATCH * 32 * 32 * C0];
__device__ float  g_lvl2 [BATCH * 16 * 16 * C0];

// ---------------- helpers ----------------
__device__ __forceinline__ float tanh_fast(float y) {     // accurate (output stage)
    float e; asm("ex2.approx.f32 %0, %1;" : "=f"(e) : "f"(y * 2.8853900817779268f));
    float r; asm("rcp.approx.f32 %0, %1;" : "=f"(r) : "f"(e + 1.0f));
    return 1.0f - 2.0f * r;
}
__device__ __forceinline__ float tanh_hw(float x) {       // 1-MUFU approx (hidden layers)
    float r; asm("tanh.approx.f32 %0, %1;" : "=f"(r) : "f"(x)); return r;
}
__device__ __forceinline__ float gelu_f(float x) {
    float u = 0.7978845608028654f * fmaf(0.044715f * x, x * x, x);
    return 0.5f * x * (1.0f + tanh_hw(u));
}
__device__ __forceinline__ void mma_f16(float* d, const uint32_t* a,
                                        uint32_t b0, uint32_t b1) {
    asm volatile(
        "mma.sync.aligned.m16n8k16.row.col.f32.f16.f16.f32 "
        "{%0,%1,%2,%3}, {%4,%5,%6,%7}, {%8,%9}, {%0,%1,%2,%3};"
        : "+f"(d[0]), "+f"(d[1]), "+f"(d[2]), "+f"(d[3])
        : "r"(a[0]), "r"(a[1]), "r"(a[2]), "r"(a[3]), "r"(b0), "r"(b1));
}
// chunk-contiguous k-permutation: within each 32-block, thread cq=(k&7)>>1 owns
// 8 contiguous halves: pos = cq*8 + s*4 + b1*2 + b0  (s=k bit4, b1=k bit3, b0=k bit0)
__device__ __host__ __forceinline__ int posf(int k) {
    return (k & ~31) | (((k >> 1) & 3) << 3) | (((k >> 4) & 1) << 2)
         | (((k >> 3) & 1) << 1) | (k & 1);
}

// ================== merged prep (one launch) ==================
// blocks [0,2048): resize lvl1; [2048,2560): resize lvl2; [2560,3584): weight
// pack; [3584,3592): FiLM ctx.

template <int HL>
__device__ void resize_body(int bid, int tid, const float* __restrict__ src) {
    int idx = bid * 256 + tid;
    int c = idx & (C0 - 1);
    int v = idx >> 6;
    int x = v % HL;
    int y = (v / HL) % HL;
    int b = v / (HL * HL);

    const float scale = (float)(GH / HL);
    const int   T     = 2 * (GH / HL);

    float sy = (y + 0.5f) * scale - 0.5f;
    float sx = (x + 0.5f) * scale - 0.5f;
    int s0y = (int)floorf(sy - scale) + 1;
    int s0x = (int)floorf(sx - scale) + 1;

    float wy[8], wx[8];
    float sumy = 0.f, sumx = 0.f;
#pragma unroll
    for (int t = 0; t < T; t++) {
        int s = s0y + t;
        float w = 1.0f - fabsf((float)s - sy) / scale;
        w = (s >= 0 && s < GH && w > 0.f) ? w : 0.f;
        wy[t] = w; sumy += w;
        s = s0x + t;
        w = 1.0f - fabsf((float)s - sx) / scale;
        w = (s >= 0 && s < GH && w > 0.f) ? w : 0.f;
        wx[t] = w; sumx += w;
    }
    float inv = 1.0f / (sumy * sumx);

    float acc = 0.f;
#pragma unroll
    for (int a = 0; a < T; a++) {
        if (wy[a] == 0.f) continue;
        const float* row = src + ((((b * GH) + (s0y + a)) * GH) << 6) + c;
        float pacc = 0.f;
#pragma unroll
        for (int t = 0; t < T; t++) {
            if (wx[t] == 0.f) continue;
            pacc += wx[t] * row[(s0x + t) << 6];
        }
        acc += wy[a] * pacc;
    }
    float* dst = (HL == 32) ? g_lvl1 : g_lvl2;
    dst[idx] = acc * inv;
}

// Weight pack, coalesced LDG layout (halves):
//   idx = [l:2][c:3][nw:2][s:1][j:2][lane:5][u:3]
//   value = W[k][n] with k = c*32 + s*16 + 2*cq + (u&1) + (((u>>1)&1)<<3),
//   n = nw*64 + (2*j + (u>>2))*8 + r   (lane = r*4+cq)
// layer-0 K remap: [0..41]->rows 0..41, [42..43] zero, [44..235]->rows 42..233,
// [236..255] zero (matches the h-tile posf layout).
__device__ void prep_wt_body(int bid, int tid,
                             const float* __restrict__ W0,
                             const float* __restrict__ W1,
                             const float* __restrict__ W2,
                             const float* __restrict__ W3) {
    int idx  = bid * 256 + tid;                // 4 * WT_L
    int u    = idx & 7;
    int lane = (idx >> 3) & 31;
    int j    = (idx >> 8) & 3;
    int s    = (idx >> 10) & 1;
    int nw   = (idx >> 11) & 3;
    int c    = (idx >> 13) & 7;
    int l    = idx >> 16;
    int r = lane >> 2, cq = lane & 3;
    int nt = 2 * j + (u >> 2);
    int q  = u & 3;
    int k = c * 32 + s * 16 + 2 * cq + (q & 1) + ((q >> 1) << 3);
    int n = nw * 64 + nt * 8 + r;
    float v = 0.0f;
    if (l == 0) {
        if (k < 42)                  v = W0[k * HID + n];
        else if (k >= 44 && k < 236) v = W0[(k - 2) * HID + n];
    } else if (l == 1) v = W1[k * HID + n];
    else if (l == 2)   v = W2[k * HID + n];
    else               v = W3[k * HID + n];
    g_WT[idx] = __float2half_rn(v);
}

__device__ void prep_ctx_body(int b, int c,
                              const float* __restrict__ cv,
                              const float* __restrict__ Wc,
                              const float* __restrict__ bc) {
    float g  = bc[c];
    float bt = bc[HID + c];
#pragma unroll 8
    for (int k = 0; k < C0; k++) {
        float v = cv[b * C0 + k];
        g  += v * Wc[k * 2 * HID + c];
        bt += v * Wc[k * 2 * HID + HID + c];
    }
    g_gamma[b * HID + c] = g + 1.0f;
    g_beta [b * HID + c] = bt;
}

__global__ void prep_all_kernel(const float* __restrict__ fg,
                                const float* __restrict__ cv,
                                const float* __restrict__ Wc,
                                const float* __restrict__ bc,
                                const float* __restrict__ W0,
                                const float* __restrict__ W1,
                                const float* __restrict__ W2,
                                const float* __restrict__ W3) {
    int bid = blockIdx.x, tid = threadIdx.x;
    if (bid < 2048)       resize_body<32>(bid, tid, fg);
    else if (bid < 2560)  resize_body<16>(bid - 2048, tid, fg);
    else if (bid < 3584)  prep_wt_body(bid - 2560, tid, W0, W1, W2, W3);
    else                  prep_ctx_body(bid - 3584, tid, cv, Wc, bc);
}

// ---------------- main fused decoder (fp16 HMMA, direct-LDG weights) -------
__global__ __launch_bounds__(THREADS, 2)
void decoder_kernel(const float* __restrict__ fg,
                    const float* __restrict__ coords,
                    const float* __restrict__ b0, const float* __restrict__ b1,
                    const float* __restrict__ b2, const float* __restrict__ b3,
                    const float* __restrict__ Wout, const float* __restrict__ bout,
                    float* __restrict__ out) {
    extern __shared__ char smem_raw[];
    __half* h_s    = (__half*)smem_raw;                       // 64 * 288
    float*  bias_s = (float*)(h_s + TILE_M * HSH);            // 4*256
    float*  gam_s  = bias_s + 4 * HID;
    float*  bet_s  = gam_s + HID;
    float*  wo_s   = bet_s + HID;                             // 3*256, straight [n][o]
    float*  bo_s   = wo_s + 3 * HID;                          // 4
    float*  red_s  = bo_s + 4;                                // 64*4*3

    const int tid  = threadIdx.x;
    const int lane = tid & 31;
    const int wid  = tid >> 5;
    const int mw   = wid & 1,  nw = wid >> 1;
    const int m0   = mw * 32,  n0 = nw * 64;
    const int r    = lane >> 2, cq = lane & 3;
    const int b    = blockIdx.x >> 8;
    const int n0p  = (blockIdx.x & 255) * TILE_M;

    // per-warp weight base (uint4 granularity, coalesced: +lane)
    const int woff = nw * 2048;          // halves within a chunk block

    // B register double buffer; prologue: load (layer0, chunk0, s0) early
    uint4 Bb[2][4];
    {
        const uint4* p = (const uint4*)(g_WT + woff) + lane;
        Bb[0][0] = p[0]; Bb[0][1] = p[32]; Bb[0][2] = p[64]; Bb[0][3] = p[96];
    }

    // stage per-CTA params
    gam_s[tid]  = g_gamma[b * HID + tid];
    bet_s[tid]  = g_beta [b * HID + tid];
    bias_s[tid]           = b0[tid];
    bias_s[HID + tid]     = b1[tid];
    bias_s[2 * HID + tid] = b2[tid];
    bias_s[3 * HID + tid] = b3[tid];
    for (int j = tid; j < 3 * HID; j += THREADS) wo_s[j] = Wout[j];
    if (tid < 3) bo_s[tid] = bout[tid];

    // ---- build features (fp16, posf-permuted k): 4 threads per point ----
    {
        int p = tid >> 2, q = tid & 3;
        float cy = coords[(n0p + p) * 2 + 0];
        float cx = coords[(n0p + p) * 2 + 1];
        __half* hp = h_s + p * HSH;

        if (q < 2) {
            // posenc via exact double-angle recurrence: one sincosf per chain.
            // q=0 handles y (channels 2+4f, 2+4f+2); q=1 handles x (+1, +3).
            float coord = (q == 0) ? cy : cx;
            float sv, cvv;
            sincosf(coord * 3.14159265358979323846f, &sv, &cvv);
#pragma unroll
            for (int f = 0; f < NFREQ; f++) {
                hp[posf(2 + 4 * f + q)]     = __float2half_rn(sv);
                hp[posf(2 + 4 * f + 2 + q)] = __float2half_rn(cvv);
                float ns = 2.0f * sv * cvv;
                float nc = 1.0f - 2.0f * sv * sv;
                sv = ns; cvv = nc;
            }
        } else if (q == 2) {
            hp[posf(0)] = __float2half_rn(cy);
            hp[posf(1)] = __float2half_rn(cx);
            hp[posf(42)] = __float2half_rn(0.f);
            hp[posf(43)] = __float2half_rn(0.f);
#pragma unroll
            for (int k = 236; k < 246; k++) hp[posf(k)] = __float2half_rn(0.f);
        } else {
#pragma unroll
            for (int k = 246; k < 256; k++) hp[posf(k)] = __float2half_rn(0.f);
        }

#pragma unroll
        for (int lvl = 0; lvl < 3; lvl++) {
            int Hl = GH >> lvl;
            const float* G = (lvl == 0) ? fg : ((lvl == 1) ? g_lvl1 : g_lvl2);
            float yf = (cy + 1.0f) * 0.5f * (float)(Hl - 1);
            float xf = (cx + 1.0f) * 0.5f * (float)(Hl - 1);
            float y0f = floorf(yf), x0f = floorf(xf);
            float wy = yf - y0f, wx = xf - x0f;
            int y0 = min(max((int)y0f, 0), Hl - 1);
            int x0 = min(max((int)x0f, 0), Hl - 1);
            int y1 = min(y0 + 1, Hl - 1);
            int x1 = min(x0 + 1, Hl - 1);
            const float* p00 = G + ((((b * Hl) + y0) * Hl + x0) << 6);
            const float* p01 = G + ((((b * Hl) + y0) * Hl + x1) << 6);
            const float* p10 = G + ((((b * Hl) + y1) * Hl + x0) << 6);
            const float* p11 = G + ((((b * Hl) + y1) * Hl + x1) << 6);
            float omx = 1.0f - wx, omy = 1.0f - wy;
            int base = 44 + lvl * 64 + q * 16;
#pragma unroll
            for (int cc = 0; cc < 4; cc++) {
                int c = q * 16 + cc * 4;
                float4 v00 = *(const float4*)(p00 + c);
                float4 v01 = *(const float4*)(p01 + c);
                float4 v10 = *(const float4*)(p10 + c);
                float4 v11 = *(const float4*)(p11 + c);
                float f0 = (v00.x * omx + v01.x * wx) * omy + (v10.x * omx + v11.x * wx) * wy;
                float f1 = (v00.y * omx + v01.y * wx) * omy + (v10.y * omx + v11.y * wx) * wy;
                float f2 = (v00.z * omx + v01.z * wx) * omy + (v10.z * omx + v11.z * wx) * wy;
                float f3 = (v00.w * omx + v01.w * wx) * omy + (v10.w * omx + v11.w * wx) * wy;
                // 4 consecutive k (k0 % 4 == 0) -> permuted positions pp, pp+1, pp+8, pp+9
                int pp = posf(base + cc * 4);
                *(__half2*)(hp + pp)     = __floats2half2_rn(f0, f1);
                *(__half2*)(hp + pp + 8) = __floats2half2_rn(f2, f3);
            }
        }
    }
    __syncthreads();    // h tile + params visible to all warps

    // ---- 4 FiLM'd MLP layers on tensor cores (fp16 m16n8k16) ----
    for (int l = 0; l < 4; l++) {
        const __half* WTl = g_WT + l * WT_L;

        float acc[2][8][4];
#pragma unroll
        for (int i = 0; i < 2; i++)
#pragma unroll
            for (int j = 0; j < 8; j++)
#pragma unroll
                for (int v = 0; v < 4; v++) acc[i][j][v] = 0.f;

#pragma unroll
        for (int c = 0; c < 8; c++) {
            // A: one LDS.128 per (mt,row-half) covers the whole 32-k chunk
            uint32_t a[2][2][4];     // [s][mt][frag]
#pragma unroll
            for (int mt = 0; mt < 2; mt++) {
                int row = m0 + mt * 16 + r;
                const char* h0 = (const char*)(h_s + row * HSH) + c * 64 + cq * 16;
                const char* h1 = (const char*)(h_s + (row + 8) * HSH) + c * 64 + cq * 16;
                uint4 A0 = *(const uint4*)h0;
                uint4 A1 = *(const uint4*)h1;
                a[0][mt][0] = A0.x; a[0][mt][1] = A1.x;
                a[0][mt][2] = A0.y; a[0][mt][3] = A1.y;
                a[1][mt][0] = A0.z; a[1][mt][1] = A1.z;
                a[1][mt][2] = A0.w; a[1][mt][3] = A1.w;
            }
#pragma unroll
            for (int s = 0; s < 2; s++) {
                const int step = c * 2 + s;
                const int cur  = step & 1;
                // prefetch next half-chunk (or next layer's first) into other buf
                if (step < 15) {
                    int ns = step + 1;
                    const uint4* np = (const uint4*)(WTl + (ns >> 1) * 8192 +
                                                     (ns & 1) * 1024 + woff) + lane;
                    Bb[cur ^ 1][0] = np[0];  Bb[cur ^ 1][1] = np[32];
                    Bb[cur ^ 1][2] = np[64]; Bb[cur ^ 1][3] = np[96];
                } else if (l < 3) {
                    const uint4* np = (const uint4*)(WTl + WT_L + woff) + lane;
                    Bb[cur ^ 1][0] = np[0];  Bb[cur ^ 1][1] = np[32];
                    Bb[cur ^ 1][2] = np[64]; Bb[cur ^ 1][3] = np[96];
                }
#pragma unroll
                for (int j = 0; j < 4; j++) {
                    uint4 B = Bb[cur][j];
                    mma_f16(acc[0][2 * j],     a[s][0], B.x, B.y);
                    mma_f16(acc[1][2 * j],     a[s][1], B.x, B.y);
                    mma_f16(acc[0][2 * j + 1], a[s][0], B.z, B.w);
                    mma_f16(acc[1][2 * j + 1], a[s][1], B.z, B.w);
                }
            }
        }
        __syncthreads();   // all A-reads of h done before epilogue writes

        if (l < 3) {
            // ---- epilogue: bias + FiLM + gelu -> fp16, write back permuted ----
#pragma unroll
            for (int nt = 0; nt < 8; nt++) {
                int n  = n0 + nt * 8 + 2 * cq;
                int pp = (n & ~31) | (cq << 3) | (((n >> 4) & 1) << 2)
                       | (((n >> 3) & 1) << 1);
                float g0 = gam_s[n],  g1 = gam_s[n + 1];
                float e0 = bet_s[n],  e1 = bet_s[n + 1];
                float i0 = bias_s[l * HID + n], i1 = bias_s[l * HID + n + 1];
#pragma unroll
                for (int mt = 0; mt < 2; mt++) {
                    int p0 = m0 + mt * 16 + r;
                    *(__half2*)(h_s + p0 * HSH + pp) = __floats2half2_rn(
                        gelu_f((acc[mt][nt][0] + i0) * g0 + e0),
                        gelu_f((acc[mt][nt][1] + i1) * g1 + e1));
                    *(__half2*)(h_s + (p0 + 8) * HSH + pp) = __floats2half2_rn(
                        gelu_f((acc[mt][nt][2] + i0) * g0 + e0),
                        gelu_f((acc[mt][nt][3] + i1) * g1 + e1));
                }
            }
            __syncthreads();
        } else {
            // ---- fused output head: gelu in regs -> xWout -> reduce ----
            float po[12];
#pragma unroll
            for (int i = 0; i < 12; i++) po[i] = 0.f;
#pragma unroll
            for (int nt = 0; nt < 8; nt++) {
                int n  = n0 + nt * 8 + 2 * cq;
                float g0c = gam_s[n],  g1c = gam_s[n + 1];
                float e0 = bet_s[n],   e1 = bet_s[n + 1];
                float i0 = bias_s[3 * HID + n], i1 = bias_s[3 * HID + n + 1];
                float w00 = wo_s[n * 3 + 0], w01 = wo_s[n * 3 + 1], w02 = wo_s[n * 3 + 2];
                float w10 = wo_s[n * 3 + 3], w11 = wo_s[n * 3 + 4], w12 = wo_s[n * 3 + 5];
#pragma unroll
                for (int mt = 0; mt < 2; mt++) {
                    float ga = gelu_f((acc[mt][nt][0] + i0) * g0c + e0);
                    float gb = gelu_f((acc[mt][nt][1] + i1) * g1c + e1);
                    float gc = gelu_f((acc[mt][nt][2] + i0) * g0c + e0);
                    float gd = gelu_f((acc[mt][nt][3] + i1) * g1c + e1);
                    int ix = mt * 6;
                    po[ix + 0] += ga * w00 + gb * w10;
                    po[ix + 1] += ga * w01 + gb * w11;
                    po[ix + 2] += ga * w02 + gb * w12;
                    po[ix + 3] += gc * w00 + gd * w10;
                    po[ix + 4] += gc * w01 + gd * w11;
                    po[ix + 5] += gc * w02 + gd * w12;
                }
            }
            // reduce across the 4 cq lanes (lane bits 0-1)
#pragma unroll
            for (int i = 0; i < 12; i++) {
                po[i] += __shfl_xor_sync(0xffffffffu, po[i], 1);
                po[i] += __shfl_xor_sync(0xffffffffu, po[i], 2);
            }
            if (cq == 0) {
#pragma unroll
                for (int mt = 0; mt < 2; mt++)
#pragma unroll
                    for (int hh = 0; hh < 2; hh++) {
                        int p = m0 + mt * 16 + hh * 8 + r;
                        float* dst = red_s + (p * 4 + nw) * 3;
                        dst[0] = po[mt * 6 + hh * 3 + 0];
                        dst[1] = po[mt * 6 + hh * 3 + 1];
                        dst[2] = po[mt * 6 + hh * 3 + 2];
                    }
            }
            __syncthreads();
            if (tid < 192) {
                int p = tid & 63, o = tid >> 6;
                const float* q4 = red_s + p * 12 + o;
                float acc2 = bo_s[o] + (q4[0] + q4[3]) + (q4[6] + q4[9]);
                out[((size_t)b * NPTS + n0p + p) * 3 + o] = tanh_fast(acc2);
            }
        }
    }
}

// ---------------- launch ----------------
extern "C" void kernel_launch(void* const* d_in, const int* in_sizes, int n_in,
                              void* d_out, int out_size) {
    const float* fg = (const float*)d_in[0];
    const float* cv = (const float*)d_in[1];
    const float* co = (const float*)d_in[2];
    const float* Wc = (const float*)d_in[3];
    const float* bc = (const float*)d_in[4];
    const float* W0 = (const float*)d_in[5];
    const float* b0 = (const float*)d_in[6];
    const float* W1 = (const float*)d_in[7];
    const float* b1 = (const float*)d_in[8];
    const float* W2 = (const float*)d_in[9];
    const float* b2 = (const float*)d_in[10];
    const float* W3 = (const float*)d_in[11];
    const float* b3 = (const float*)d_in[12];
    const float* Wo = (const float*)d_in[13];
    const float* bo = (const float*)d_in[14];
    float* out = (float*)d_out;

    const int smemB = TILE_M * HSH * 2 +
                      (4 * HID + HID + HID + 3 * HID + 4 + 64 * 12) * 4;
    cudaFuncSetAttribute(decoder_kernel,
                         cudaFuncAttributeMaxDynamicSharedMemorySize, smemB);

    prep_all_kernel<<<3592, 256>>>(fg, cv, Wc, bc, W0, W1, W2, W3);
    decoder_kernel<<<BATCH * (NPTS / TILE_M), THREADS, smemB>>>(
        fg, co, b0, b1, b2, b3, Wo, bo, out);
}